// round 11
// baseline (speedup 1.0000x reference)
#include <cuda_runtime.h>
#include <math.h>

#define EPSF 1e-8f
#define BIGF 1e10f
#define MAXB 8
#define MAXF 4096

#define TILE_W 8
#define TILE_H 8
#define NT_R   128         // 4 warps; each warp covers all 64 px, 1/4 of list
#define NWARPS 4

#define MAXBL    4         // batches supported by the bin lists
#define MAXTILES 1024      // 32x32 tiles for 256x256 at 8x8
#define CAP      2048      // per-tile list capacity (> F always)
#define CH       32        // per-warp chunk size

// Scratch (device globals; zero-initialized at load; raster restores zeros
// so every graph replay sees identical state)
__device__ float4 g_tri[MAXB * MAXF * 4];       // d0,d1,d2,d3 per triangle (indexed by face id)
__device__ int    g_partcnt[MAXBL * MAXTILES];  // partial-coverage entries (front of list)
__device__ int    g_fullcnt[MAXBL * MAXTILES];  // full-coverage entries (back of list)
__device__ int    g_tilelist[MAXBL * MAXTILES * CAP];

// Conservative interval of affine w over a pixel-center rectangle:
// wc at rect center, radius = |ex|*hy + |ey|*hx, padded for fp slop.
__device__ __forceinline__ void edge_range(float ex, float ey, float ax, float ay,
                                           float cx, float cy, float hx, float hy,
                                           float& wmin, float& wmax) {
    float wc = ex * (cy - ay) - ey * (cx - ax);
    float r  = fabsf(ex) * hy + fabsf(ey) * hx;
    float pad = 1e-5f * (fabsf(wc) + r) + 1e-5f;
    wmin = wc - r - pad;
    wmax = wc + r + pad;
}

// Fused setup + bin. One thread per (batch, face): project vertices, build
// edge-function setup (stored at face index, no compaction), cull invalid
// triangles, then walk the bbox tile range pushing entries into per-tile
// lists — partial-coverage at the front, full-coverage at the back.
__global__ void dr_setup_bin_kernel(const float* __restrict__ mesh,
                                    const float* __restrict__ Rm,
                                    const float* __restrict__ tv,
                                    const float* __restrict__ focal,
                                    const float* __restrict__ princpt,
                                    const int*   __restrict__ face,
                                    int B, int V, int F, int ntx, int nty) {
    int idx = blockIdx.x * blockDim.x + threadIdx.x;
    if (idx >= B * F) return;
    int b = idx / F;
    int f = idx - b * F;

    const float* Rb = Rm + b * 9;
    float t0 = tv[b * 3 + 0], t1 = tv[b * 3 + 1], t2 = tv[b * 3 + 2];
    float fx = focal[b * 2 + 0], fy = focal[b * 2 + 1];
    float cx = princpt[b * 2 + 0], cy = princpt[b * 2 + 1];

    float X[3], Y[3], Z[3];
#pragma unroll
    for (int k = 0; k < 3; k++) {
        int v = face[f * 3 + k];
        const float* m = mesh + ((long)b * V + v) * 3;
        float m0 = m[0], m1 = m[1], m2 = m[2];
        // einsum sum order j=0..2, then + t  (exact rn ops, no contraction)
        float c0 = __fadd_rn(__fadd_rn(__fmul_rn(Rb[0], m0), __fmul_rn(Rb[1], m1)), __fmul_rn(Rb[2], m2));
        float c1 = __fadd_rn(__fadd_rn(__fmul_rn(Rb[3], m0), __fmul_rn(Rb[4], m1)), __fmul_rn(Rb[5], m2));
        float c2 = __fadd_rn(__fadd_rn(__fmul_rn(Rb[6], m0), __fmul_rn(Rb[7], m1)), __fmul_rn(Rb[8], m2));
        c0 = __fadd_rn(c0, t0);
        c1 = __fadd_rn(c1, t1);
        c2 = __fadd_rn(c2, t2);
        float zs = (fabsf(c2) > EPSF) ? c2 : EPSF;
        X[k] = __fadd_rn(__fdiv_rn(__fmul_rn(fx, c0), zs), cx);
        Y[k] = __fadd_rn(__fdiv_rn(__fmul_rn(fy, c1), zs), cy);
        Z[k] = c2;
    }

    // area = (x1-x0)*(y2-y0) - (y1-y0)*(x2-x0)   (reference rounding)
    float area = __fsub_rn(__fmul_rn(__fsub_rn(X[1], X[0]), __fsub_rn(Y[2], Y[0])),
                           __fmul_rn(__fsub_rn(Y[1], Y[0]), __fsub_rn(X[2], X[0])));
    if (!(fabsf(area) > EPSF)) return;                       // invalid area -> never contributes
    if (!(fminf(Z[0], fminf(Z[1], Z[2])) > EPSF)) return;    // not front -> never contributes

    float iz0 = __fdiv_rn(Z[0], area);
    float iz1 = __fdiv_rn(Z[1], area);
    float iz2 = __fdiv_rn(Z[2], area);

    float4 e0 = make_float4(__fsub_rn(X[2], X[1]), __fsub_rn(Y[2], Y[1]), X[1], Y[1]);
    float4 e1 = make_float4(__fsub_rn(X[0], X[2]), __fsub_rn(Y[0], Y[2]), X[2], Y[2]);
    float4 e2 = make_float4(__fsub_rn(X[1], X[0]), __fsub_rn(Y[1], Y[0]), X[0], Y[0]);

    float4* o = &g_tri[((long)b * MAXF + f) * 4];
    o[0] = e0;
    o[1] = e1;
    o[2] = e2;
    o[3] = make_float4(iz0, iz1, iz2, 0.f);

    float xmin = fminf(X[0], fminf(X[1], X[2]));
    float xmax = fmaxf(X[0], fmaxf(X[1], X[2]));
    float ymin = fminf(Y[0], fminf(Y[1], Y[2]));
    float ymax = fmaxf(Y[0], fmaxf(Y[1], Y[2]));

    // conservative candidate tile range (extra tiles rejected by tests below)
    int tx0 = max(0, (int)floorf((xmin - ((float)TILE_W - 0.5f)) * (1.f / TILE_W)));
    int tx1 = min(ntx - 1, (int)floorf((xmax - 0.5f) * (1.f / TILE_W)) + 1);
    int ty0 = max(0, (int)floorf((ymin - ((float)TILE_H - 0.5f)) * (1.f / TILE_H)));
    int ty1 = min(nty - 1, (int)floorf((ymax - 0.5f) * (1.f / TILE_H)) + 1);

    for (int tiley = ty0; tiley <= ty1; tiley++) {
        for (int tilex = tx0; tilex <= tx1; tilex++) {
            float tminx = (float)(tilex * TILE_W) + 0.5f;
            float tmaxx = (float)(tilex * TILE_W + TILE_W - 1) + 0.5f;
            float tminy = (float)(tiley * TILE_H) + 0.5f;
            float tmaxy = (float)(tiley * TILE_H + TILE_H - 1) + 0.5f;
            // bbox pre-filter (same as before)
            if (xmax >= tminx && xmin <= tmaxx && ymax >= tminy && ymin <= tmaxy) {
                float tcx = 0.5f * (tminx + tmaxx);
                float tcy = 0.5f * (tminy + tmaxy);
                float thx = 0.5f * (tmaxx - tminx);
                float thy = 0.5f * (tmaxy - tminy);
                float mn0, mx0, mn1, mx1, mn2, mx2;
                edge_range(e0.x, e0.y, e0.z, e0.w, tcx, tcy, thx, thy, mn0, mx0);
                edge_range(e1.x, e1.y, e1.z, e1.w, tcx, tcy, thx, thy, mn1, mx1);
                edge_range(e2.x, e2.y, e2.z, e2.w, tcx, tcy, thx, thy, mn2, mx2);
                bool pos_ok = (mx0 >= 0.f) && (mx1 >= 0.f) && (mx2 >= 0.f);
                bool neg_ok = (mn0 <= 0.f) && (mn1 <= 0.f) && (mn2 <= 0.f);
                if (pos_ok || neg_ok) {
                    // full coverage: even the padded worst case keeps uniform sign
                    bool full = ((mn0 >= 0.f) && (mn1 >= 0.f) && (mn2 >= 0.f)) ||
                                ((mx0 <= 0.f) && (mx1 <= 0.f) && (mx2 <= 0.f));
                    int slot = b * MAXTILES + tiley * ntx + tilex;
                    if (full) {
                        int p = atomicAdd(&g_fullcnt[slot], 1);
                        g_tilelist[(long)slot * CAP + (CAP - 1 - p)] = f;
                    } else {
                        int p = atomicAdd(&g_partcnt[slot], 1);
                        g_tilelist[(long)slot * CAP + p] = f;
                    }
                }
            }
        }
    }
}

// 8x8 pixel tile per block, 128 threads = 4 warps. Every warp covers all 64
// pixels (2 adjacent px/lane) but processes a disjoint quarter of each list
// segment. Two homogeneous loops: partial entries (with inside test) from the
// front, full entries (test elided — guaranteed by padded classification)
// from the back. No per-iteration branching. Partial z-mins merge in SMEM,
// direct write to out. Block re-zeroes its counters (replay-safe).
__global__ __launch_bounds__(NT_R)
void dr_raster_kernel(float* __restrict__ out, int W, int H, int ntx) {
    __shared__ float4 sdata[NWARPS][CH * 4];
    __shared__ int    sidx[NWARPS][CH];
    __shared__ float  szmin[NWARPS][65];   // [warp][pixel], padded
    __shared__ int    scnt[2];

    int b = blockIdx.z;
    int tile = blockIdx.y * ntx + blockIdx.x;
    int slot = b * MAXTILES + tile;

    int tid  = threadIdx.x;
    int warp = tid >> 5;
    int lane = tid & 31;

    if (tid == 0) {
        scnt[0] = g_partcnt[slot];
        scnt[1] = g_fullcnt[slot];
        g_partcnt[slot] = 0;                 // restore zeros for next replay
        g_fullcnt[slot] = 0;
    }
    __syncthreads();
    int count_p = scnt[0];
    int count_f = scnt[1];

    // lane -> 2 adjacent pixels on one row: p0 = 2*lane, p1 = 2*lane+1
    int p0 = lane * 2;
    int prow = p0 >> 3;          // 0..7
    int pcol = p0 & 7;           // 0,2,4,6

    int row  = blockIdx.y * TILE_H + prow;
    int col0 = blockIdx.x * TILE_W + pcol;
    float py  = (float)row + 0.5f;
    float px0 = (float)col0 + 0.5f;
    float px1 = px0 + 1.0f;

    float zmin0 = BIGF, zmin1 = BIGF;

    const int*    list  = &g_tilelist[(long)slot * CAP];
    const int*    flist = list + (CAP - count_f);   // full segment, contiguous
    const float4* tri   = &g_tri[(long)b * MAXF * 4];

    // ---- partial-coverage entries: with inside test ----
    for (int base = warp * CH; base < count_p; base += NWARPS * CH) {
        int n = min(CH, count_p - base);
        if (lane < n) sidx[warp][lane] = list[base + lane];
        __syncwarp();
        for (int i = lane; i < n * 4; i += 32)
            sdata[warp][i] = tri[(long)sidx[warp][i >> 2] * 4 + (i & 3)];
        __syncwarp();

        for (int j = 0; j < n; j++) {
            float4 d0 = sdata[warp][j * 4 + 0];
            float4 d1 = sdata[warp][j * 4 + 1];
            float4 d2 = sdata[warp][j * 4 + 2];
            float4 d3 = sdata[warp][j * 4 + 3];
            // row-shared terms (reference rounding preserved)
            float a0 = __fmul_rn(d0.x, __fsub_rn(py, d0.w));
            float a1 = __fmul_rn(d1.x, __fsub_rn(py, d1.w));
            float a2 = __fmul_rn(d2.x, __fsub_rn(py, d2.w));
            {
                float w0 = __fsub_rn(a0, __fmul_rn(d0.y, __fsub_rn(px0, d0.z)));
                float w1 = __fsub_rn(a1, __fmul_rn(d1.y, __fsub_rn(px0, d1.z)));
                float w2 = __fsub_rn(a2, __fmul_rn(d2.y, __fsub_rn(px0, d2.z)));
                float wmn = fminf(fminf(w0, w1), w2);
                float wmx = fmaxf(fmaxf(w0, w1), w2);
                bool inside = (wmn >= 0.f) || (wmx <= 0.f);
                float zi = __fmaf_rn(w0, d3.x, __fmaf_rn(w1, d3.y, __fmul_rn(w2, d3.z)));
                if (inside && zi > EPSF) zmin0 = fminf(zmin0, zi);
            }
            {
                float w0 = __fsub_rn(a0, __fmul_rn(d0.y, __fsub_rn(px1, d0.z)));
                float w1 = __fsub_rn(a1, __fmul_rn(d1.y, __fsub_rn(px1, d1.z)));
                float w2 = __fsub_rn(a2, __fmul_rn(d2.y, __fsub_rn(px1, d2.z)));
                float wmn = fminf(fminf(w0, w1), w2);
                float wmx = fmaxf(fmaxf(w0, w1), w2);
                bool inside = (wmn >= 0.f) || (wmx <= 0.f);
                float zi = __fmaf_rn(w0, d3.x, __fmaf_rn(w1, d3.y, __fmul_rn(w2, d3.z)));
                if (inside && zi > EPSF) zmin1 = fminf(zmin1, zi);
            }
        }
        __syncwarp();
    }

    // ---- full-coverage entries: inside guaranteed, no test ----
    for (int base = warp * CH; base < count_f; base += NWARPS * CH) {
        int n = min(CH, count_f - base);
        if (lane < n) sidx[warp][lane] = flist[base + lane];
        __syncwarp();
        for (int i = lane; i < n * 4; i += 32)
            sdata[warp][i] = tri[(long)sidx[warp][i >> 2] * 4 + (i & 3)];
        __syncwarp();

        for (int j = 0; j < n; j++) {
            float4 d0 = sdata[warp][j * 4 + 0];
            float4 d1 = sdata[warp][j * 4 + 1];
            float4 d2 = sdata[warp][j * 4 + 2];
            float4 d3 = sdata[warp][j * 4 + 3];
            float a0 = __fmul_rn(d0.x, __fsub_rn(py, d0.w));
            float a1 = __fmul_rn(d1.x, __fsub_rn(py, d1.w));
            float a2 = __fmul_rn(d2.x, __fsub_rn(py, d2.w));
            {
                float w0 = __fsub_rn(a0, __fmul_rn(d0.y, __fsub_rn(px0, d0.z)));
                float w1 = __fsub_rn(a1, __fmul_rn(d1.y, __fsub_rn(px0, d1.z)));
                float w2 = __fsub_rn(a2, __fmul_rn(d2.y, __fsub_rn(px0, d2.z)));
                float zi = __fmaf_rn(w0, d3.x, __fmaf_rn(w1, d3.y, __fmul_rn(w2, d3.z)));
                if (zi > EPSF) zmin0 = fminf(zmin0, zi);
            }
            {
                float w0 = __fsub_rn(a0, __fmul_rn(d0.y, __fsub_rn(px1, d0.z)));
                float w1 = __fsub_rn(a1, __fmul_rn(d1.y, __fsub_rn(px1, d1.z)));
                float w2 = __fsub_rn(a2, __fmul_rn(d2.y, __fsub_rn(px1, d2.z)));
                float zi = __fmaf_rn(w0, d3.x, __fmaf_rn(w1, d3.y, __fmul_rn(w2, d3.z)));
                if (zi > EPSF) zmin1 = fminf(zmin1, zi);
            }
        }
        __syncwarp();
    }

    // merge 4 warps' partial minima
    szmin[warp][p0]     = zmin0;
    szmin[warp][p0 + 1] = zmin1;
    __syncthreads();

    if (tid < 64) {
        int p = tid;
        float z = fminf(fminf(szmin[0][p], szmin[1][p]),
                        fminf(szmin[2][p], szmin[3][p]));
        int r = blockIdx.y * TILE_H + (p >> 3);
        int c = blockIdx.x * TILE_W + (p & 7);
        if (r < H && c < W) {
            long off = ((long)b * H + r) * W + c;
            out[off] = (z < 0.5f * BIGF) ? z : -1.f;
        }
    }
}

extern "C" void kernel_launch(void* const* d_in, const int* in_sizes, int n_in,
                              void* d_out, int out_size) {
    const float* mesh    = (const float*)d_in[0];
    const float* Rm      = (const float*)d_in[1];
    const float* tv      = (const float*)d_in[2];
    const float* focal   = (const float*)d_in[3];
    const float* princpt = (const float*)d_in[4];
    const int*   face    = (const int*)  d_in[5];
    float* out = (float*)d_out;

    int B = in_sizes[1] / 9;            // R is (B,3,3)
    int V = in_sizes[0] / (3 * B);      // mesh is (B,V,3)
    int F = in_sizes[5] / 3;            // face is (F,3)
    int HW = out_size / B;              // out is (B,1,H,W)
    int W = (int)(sqrt((double)HW) + 0.5);
    int H = HW / W;
    int ntx = (W + TILE_W - 1) / TILE_W;
    int nty = (H + TILE_H - 1) / TILE_H;

    int nset = B * F;
    dr_setup_bin_kernel<<<(nset + 127) / 128, 128>>>(mesh, Rm, tv, focal, princpt,
                                                     face, B, V, F, ntx, nty);
    dim3 grid(ntx, nty, B);
    dr_raster_kernel<<<grid, NT_R>>>(out, W, H, ntx);
}

// round 12
// speedup vs baseline: 1.9796x; 1.9796x over previous
#include <cuda_runtime.h>
#include <math.h>

#define EPSF 1e-8f
#define BIGF 1e10f
#define MAXB 8
#define MAXF 4096

#define TILE_W 8
#define TILE_H 8
#define NT_R   128         // 4 warps; each warp covers all 64 px, 1/4 of list
#define NWARPS 4
#define NT     128         // setup_bin block size (128 faces per block)

#define MAXBL    4         // batches supported by the bin lists
#define MAXTILES 1024      // 32x32 tiles for 256x256 at 8x8
#define CAP      2048      // per-tile list capacity (> F always)
#define CH       64        // per-warp chunk size

// Scratch (device globals; zero-initialized at load; raster restores zeros
// so every graph replay sees identical state)
__device__ float4 g_tri[MAXB * MAXF * 4];       // e0,e1,e2,iz per triangle (indexed by face id)
__device__ int    g_tilecnt[MAXBL * MAXTILES];
__device__ int    g_tilelist[MAXBL * MAXTILES * CAP];

// Conservative interval of affine w over a pixel-center rectangle:
// wc at rect center, radius = |ex|*hy + |ey|*hx, padded for fp slop.
__device__ __forceinline__ void edge_range(float ex, float ey, float ax, float ay,
                                           float cx, float cy, float hx, float hy,
                                           float& wmin, float& wmax) {
    float wc = ex * (cy - ay) - ey * (cx - ax);
    float r  = fabsf(ex) * hy + fabsf(ey) * hx;
    float pad = 1e-5f * (fabsf(wc) + r) + 1e-5f;
    wmin = wc - r - pad;
    wmax = wc + r + pad;
}

// Fused setup + bin.
// Phase 1 (thread-per-face): project vertices, build edge setup, cull invalid
// triangles; write setup to g_tri (by face id) and to SMEM.
// Phase 2 (warp-per-triangle): warp w walks faces w, w+NWARPS, ... of this
// block; 32 lanes in parallel over the candidate tile range push face ids
// into per-tile lists (atomics pipelined across lanes — the fast R9 pattern).
__global__ __launch_bounds__(NT)
void dr_setup_bin_kernel(const float* __restrict__ mesh,
                         const float* __restrict__ Rm,
                         const float* __restrict__ tv,
                         const float* __restrict__ focal,
                         const float* __restrict__ princpt,
                         const int*   __restrict__ face,
                         int B, int V, int F, int ntx, int nty) {
    __shared__ float4 se0[NT], se1[NT], se2[NT];
    __shared__ float4 sbb[NT];          // xmin,xmax,ymin,ymax
    __shared__ int    sfb[NT];          // face id | valid<<31 ... store f, b packed
    __shared__ int    svalid[NT];

    int tid = threadIdx.x;
    int idx = blockIdx.x * NT + tid;
    int valid = 0;
    int b = 0, f = 0;

    if (idx < B * F) {
        b = idx / F;
        f = idx - b * F;

        const float* Rb = Rm + b * 9;
        float t0 = tv[b * 3 + 0], t1 = tv[b * 3 + 1], t2 = tv[b * 3 + 2];
        float fx = focal[b * 2 + 0], fy = focal[b * 2 + 1];
        float cx = princpt[b * 2 + 0], cy = princpt[b * 2 + 1];

        float X[3], Y[3], Z[3];
#pragma unroll
        for (int k = 0; k < 3; k++) {
            int v = face[f * 3 + k];
            const float* m = mesh + ((long)b * V + v) * 3;
            float m0 = m[0], m1 = m[1], m2 = m[2];
            // einsum sum order j=0..2, then + t  (exact rn ops, no contraction)
            float c0 = __fadd_rn(__fadd_rn(__fmul_rn(Rb[0], m0), __fmul_rn(Rb[1], m1)), __fmul_rn(Rb[2], m2));
            float c1 = __fadd_rn(__fadd_rn(__fmul_rn(Rb[3], m0), __fmul_rn(Rb[4], m1)), __fmul_rn(Rb[5], m2));
            float c2 = __fadd_rn(__fadd_rn(__fmul_rn(Rb[6], m0), __fmul_rn(Rb[7], m1)), __fmul_rn(Rb[8], m2));
            c0 = __fadd_rn(c0, t0);
            c1 = __fadd_rn(c1, t1);
            c2 = __fadd_rn(c2, t2);
            float zs = (fabsf(c2) > EPSF) ? c2 : EPSF;
            X[k] = __fadd_rn(__fdiv_rn(__fmul_rn(fx, c0), zs), cx);
            Y[k] = __fadd_rn(__fdiv_rn(__fmul_rn(fy, c1), zs), cy);
            Z[k] = c2;
        }

        // area = (x1-x0)*(y2-y0) - (y1-y0)*(x2-x0)   (reference rounding)
        float area = __fsub_rn(__fmul_rn(__fsub_rn(X[1], X[0]), __fsub_rn(Y[2], Y[0])),
                               __fmul_rn(__fsub_rn(Y[1], Y[0]), __fsub_rn(X[2], X[0])));
        if ((fabsf(area) > EPSF) && (fminf(Z[0], fminf(Z[1], Z[2])) > EPSF)) {
            valid = 1;
            float iz0 = __fdiv_rn(Z[0], area);
            float iz1 = __fdiv_rn(Z[1], area);
            float iz2 = __fdiv_rn(Z[2], area);

            float4 e0 = make_float4(__fsub_rn(X[2], X[1]), __fsub_rn(Y[2], Y[1]), X[1], Y[1]);
            float4 e1 = make_float4(__fsub_rn(X[0], X[2]), __fsub_rn(Y[0], Y[2]), X[2], Y[2]);
            float4 e2 = make_float4(__fsub_rn(X[1], X[0]), __fsub_rn(Y[1], Y[0]), X[0], Y[0]);

            float4* o = &g_tri[((long)b * MAXF + f) * 4];
            o[0] = e0;
            o[1] = e1;
            o[2] = e2;
            o[3] = make_float4(iz0, iz1, iz2, 0.f);

            se0[tid] = e0;
            se1[tid] = e1;
            se2[tid] = e2;
            sbb[tid] = make_float4(fminf(X[0], fminf(X[1], X[2])),
                                   fmaxf(X[0], fmaxf(X[1], X[2])),
                                   fminf(Y[0], fminf(Y[1], Y[2])),
                                   fmaxf(Y[0], fmaxf(Y[1], Y[2])));
            sfb[tid] = b * MAXTILES;   // slot base
        }
    }
    svalid[tid] = valid ? f : -1;
    __syncthreads();

    // Phase 2: warp-per-triangle over this block's faces
    int warp = tid >> 5;
    int lane = tid & 31;
    for (int lf = warp; lf < NT; lf += NWARPS) {
        int fid = svalid[lf];
        if (fid < 0) continue;
        float4 bb = sbb[lf];
        float4 e0 = se0[lf], e1 = se1[lf], e2 = se2[lf];
        int slotbase = sfb[lf];

        // conservative candidate tile range (extra tiles rejected below)
        int tx0 = max(0, (int)floorf((bb.x - ((float)TILE_W - 0.5f)) * (1.f / TILE_W)));
        int tx1 = min(ntx - 1, (int)floorf((bb.y - 0.5f) * (1.f / TILE_W)) + 1);
        int ty0 = max(0, (int)floorf((bb.z - ((float)TILE_H - 0.5f)) * (1.f / TILE_H)));
        int ty1 = min(nty - 1, (int)floorf((bb.w - 0.5f) * (1.f / TILE_H)) + 1);
        if (tx1 < tx0 || ty1 < ty0) continue;
        int nx = tx1 - tx0 + 1;
        int ntiles = nx * (ty1 - ty0 + 1);

        for (int i = lane; i < ntiles; i += 32) {
            int tilex = tx0 + (i % nx);
            int tiley = ty0 + (i / nx);
            float tminx = (float)(tilex * TILE_W) + 0.5f;
            float tmaxx = (float)(tilex * TILE_W + TILE_W - 1) + 0.5f;
            float tminy = (float)(tiley * TILE_H) + 0.5f;
            float tmaxy = (float)(tiley * TILE_H + TILE_H - 1) + 0.5f;
            // bbox pre-filter (same as before)
            if (bb.y >= tminx && bb.x <= tmaxx && bb.w >= tminy && bb.z <= tmaxy) {
                float tcx = 0.5f * (tminx + tmaxx);
                float tcy = 0.5f * (tminy + tmaxy);
                float thx = 0.5f * (tmaxx - tminx);
                float thy = 0.5f * (tmaxy - tminy);
                float mn0, mx0, mn1, mx1, mn2, mx2;
                edge_range(e0.x, e0.y, e0.z, e0.w, tcx, tcy, thx, thy, mn0, mx0);
                edge_range(e1.x, e1.y, e1.z, e1.w, tcx, tcy, thx, thy, mn1, mx1);
                edge_range(e2.x, e2.y, e2.z, e2.w, tcx, tcy, thx, thy, mn2, mx2);
                bool pos_ok = (mx0 >= 0.f) && (mx1 >= 0.f) && (mx2 >= 0.f);
                bool neg_ok = (mn0 <= 0.f) && (mn1 <= 0.f) && (mn2 <= 0.f);
                if (pos_ok || neg_ok) {
                    int slot = slotbase + tiley * ntx + tilex;
                    int p = atomicAdd(&g_tilecnt[slot], 1);   // p < F <= CAP always
                    g_tilelist[(long)slot * CAP + p] = fid;
                }
            }
        }
    }
}

// 8x8 pixel tile per block, 128 threads = 4 warps. Every warp covers all 64
// pixels (2 adjacent px/lane) but processes a disjoint quarter of the tile's
// triangle list (interleaved CH-chunks, per-warp SMEM staging). Partial z-mins
// merge in SMEM (fminf, order-independent) then write directly to out.
// Block re-zeroes its tilecnt slot (self-cleaning for graph replay).
__global__ __launch_bounds__(NT_R)
void dr_raster_kernel(float* __restrict__ out, int W, int H, int ntx) {
    __shared__ float4 sdata[NWARPS][CH * 4];
    __shared__ int    sidx[NWARPS][CH];
    __shared__ float  szmin[NWARPS][65];   // [warp][pixel], padded
    __shared__ int    scount;

    int b = blockIdx.z;
    int tile = blockIdx.y * ntx + blockIdx.x;
    int slot = b * MAXTILES + tile;

    int tid  = threadIdx.x;
    int warp = tid >> 5;
    int lane = tid & 31;

    if (tid == 0) {
        scount = g_tilecnt[slot];
        g_tilecnt[slot] = 0;                 // restore zero for next replay
    }
    __syncthreads();
    int count = scount;

    // lane -> 2 adjacent pixels on one row: p0 = 2*lane, p1 = 2*lane+1
    int p0 = lane * 2;
    int prow = p0 >> 3;          // 0..7
    int pcol = p0 & 7;           // 0,2,4,6

    int row  = blockIdx.y * TILE_H + prow;
    int col0 = blockIdx.x * TILE_W + pcol;
    float py  = (float)row + 0.5f;
    float px0 = (float)col0 + 0.5f;
    float px1 = px0 + 1.0f;

    float zmin0 = BIGF, zmin1 = BIGF;

    const int*    list = &g_tilelist[(long)slot * CAP];
    const float4* tri  = &g_tri[(long)b * MAXF * 4];

    // warp w processes chunks w, w+4, w+8, ...
    for (int base = warp * CH; base < count; base += NWARPS * CH) {
        int n = min(CH, count - base);
        for (int i = lane; i < n; i += 32) sidx[warp][i] = list[base + i];
        __syncwarp();
        for (int i = lane; i < n * 4; i += 32)
            sdata[warp][i] = tri[(long)sidx[warp][i >> 2] * 4 + (i & 3)];
        __syncwarp();

        for (int j = 0; j < n; j++) {
            float4 d0 = sdata[warp][j * 4 + 0];
            float4 d1 = sdata[warp][j * 4 + 1];
            float4 d2 = sdata[warp][j * 4 + 2];
            float4 d3 = sdata[warp][j * 4 + 3];
            // row-shared terms (reference rounding preserved)
            float a0 = __fmul_rn(d0.x, __fsub_rn(py, d0.w));
            float a1 = __fmul_rn(d1.x, __fsub_rn(py, d1.w));
            float a2 = __fmul_rn(d2.x, __fsub_rn(py, d2.w));
            // pixel 0
            {
                float w0 = __fsub_rn(a0, __fmul_rn(d0.y, __fsub_rn(px0, d0.z)));
                float w1 = __fsub_rn(a1, __fmul_rn(d1.y, __fsub_rn(px0, d1.z)));
                float w2 = __fsub_rn(a2, __fmul_rn(d2.y, __fsub_rn(px0, d2.z)));
                float wmn = fminf(fminf(w0, w1), w2);
                float wmx = fmaxf(fmaxf(w0, w1), w2);
                bool inside = (wmn >= 0.f) || (wmx <= 0.f);
                float zi = __fmaf_rn(w0, d3.x, __fmaf_rn(w1, d3.y, __fmul_rn(w2, d3.z)));
                if (inside && zi > EPSF) zmin0 = fminf(zmin0, zi);
            }
            // pixel 1
            {
                float w0 = __fsub_rn(a0, __fmul_rn(d0.y, __fsub_rn(px1, d0.z)));
                float w1 = __fsub_rn(a1, __fmul_rn(d1.y, __fsub_rn(px1, d1.z)));
                float w2 = __fsub_rn(a2, __fmul_rn(d2.y, __fsub_rn(px1, d2.z)));
                float wmn = fminf(fminf(w0, w1), w2);
                float wmx = fmaxf(fmaxf(w0, w1), w2);
                bool inside = (wmn >= 0.f) || (wmx <= 0.f);
                float zi = __fmaf_rn(w0, d3.x, __fmaf_rn(w1, d3.y, __fmul_rn(w2, d3.z)));
                if (inside && zi > EPSF) zmin1 = fminf(zmin1, zi);
            }
        }
        __syncwarp();
    }

    // merge 4 warps' partial minima
    szmin[warp][p0]     = zmin0;
    szmin[warp][p0 + 1] = zmin1;
    __syncthreads();

    if (tid < 64) {
        int p = tid;
        float z = fminf(fminf(szmin[0][p], szmin[1][p]),
                        fminf(szmin[2][p], szmin[3][p]));
        int r = blockIdx.y * TILE_H + (p >> 3);
        int c = blockIdx.x * TILE_W + (p & 7);
        if (r < H && c < W) {
            long off = ((long)b * H + r) * W + c;
            out[off] = (z < 0.5f * BIGF) ? z : -1.f;
        }
    }
}

extern "C" void kernel_launch(void* const* d_in, const int* in_sizes, int n_in,
                              void* d_out, int out_size) {
    const float* mesh    = (const float*)d_in[0];
    const float* Rm      = (const float*)d_in[1];
    const float* tv      = (const float*)d_in[2];
    const float* focal   = (const float*)d_in[3];
    const float* princpt = (const float*)d_in[4];
    const int*   face    = (const int*)  d_in[5];
    float* out = (float*)d_out;

    int B = in_sizes[1] / 9;            // R is (B,3,3)
    int V = in_sizes[0] / (3 * B);      // mesh is (B,V,3)
    int F = in_sizes[5] / 3;            // face is (F,3)
    int HW = out_size / B;              // out is (B,1,H,W)
    int W = (int)(sqrt((double)HW) + 0.5);
    int H = HW / W;
    int ntx = (W + TILE_W - 1) / TILE_W;
    int nty = (H + TILE_H - 1) / TILE_H;

    int nset = B * F;
    dr_setup_bin_kernel<<<(nset + NT - 1) / NT, NT>>>(mesh, Rm, tv, focal, princpt,
                                                      face, B, V, F, ntx, nty);
    dim3 grid(ntx, nty, B);
    dr_raster_kernel<<<grid, NT_R>>>(out, W, H, ntx);
}

// round 13
// speedup vs baseline: 5.9535x; 3.0074x over previous
#include <cuda_runtime.h>
#include <math.h>

#define EPSF 1e-8f
#define BIGF 1e10f
#define MAXB 8
#define MAXF 4096

#define TILE_W 8
#define TILE_H 8
#define NT_R   128         // raster: 4 warps; each covers all 64 px, 1/4 of list
#define NWARPS 4
#define NT     128         // setup_bin block size (4 warps = 4 faces per block)

#define MAXBL    4         // batches supported by the bin lists
#define MAXTILES 1024      // 32x32 tiles for 256x256 at 8x8
#define CAP      2048      // per-tile list capacity (> F always)
#define CH       32        // per-warp chunk size (raster)

// Scratch (device globals; zero-initialized at load; raster restores zeros
// so every graph replay sees identical state)
__device__ float4 g_tri[MAXB * MAXF * 4];       // e0,e1,e2,iz per triangle (by face id)
__device__ int    g_tilecnt[MAXBL * MAXTILES];
__device__ int    g_tilelist[MAXBL * MAXTILES * CAP];

// Conservative interval of affine w over a pixel-center rectangle:
// wc at rect center, radius = |ex|*hy + |ey|*hx, padded for fp slop.
__device__ __forceinline__ void edge_range(float ex, float ey, float ax, float ay,
                                           float cx, float cy, float hx, float hy,
                                           float& wmin, float& wmax) {
    float wc = ex * (cy - ay) - ey * (cx - ax);
    float r  = fabsf(ex) * hy + fabsf(ey) * hx;
    float pad = 1e-5f * (fabsf(wc) + r) + 1e-5f;
    wmin = wc - r - pad;
    wmax = wc + r + pad;
}

// Fused setup + bin, ONE WARP PER (batch, face) — R9's bin parallelism.
// All 32 lanes redundantly compute the projection/edge setup (SIMT-free),
// lanes 0-3 store the 4 float4s of g_tri, then the 32 lanes walk the
// candidate tile range in parallel pushing the face id into per-tile lists.
__global__ __launch_bounds__(NT)
void dr_setup_bin_kernel(const float* __restrict__ mesh,
                         const float* __restrict__ Rm,
                         const float* __restrict__ tv,
                         const float* __restrict__ focal,
                         const float* __restrict__ princpt,
                         const int*   __restrict__ face,
                         int B, int V, int F, int ntx, int nty) {
    int warp = threadIdx.x >> 5;
    int lane = threadIdx.x & 31;
    int idx = blockIdx.x * (NT / 32) + warp;      // global warp id = (b,f)
    if (idx >= B * F) return;
    int b = idx / F;
    int f = idx - b * F;

    const float* Rb = Rm + b * 9;
    float t0 = tv[b * 3 + 0], t1 = tv[b * 3 + 1], t2 = tv[b * 3 + 2];
    float fx = focal[b * 2 + 0], fy = focal[b * 2 + 1];
    float cx = princpt[b * 2 + 0], cy = princpt[b * 2 + 1];

    float X[3], Y[3], Z[3];
#pragma unroll
    for (int k = 0; k < 3; k++) {
        int v = face[f * 3 + k];
        const float* m = mesh + ((long)b * V + v) * 3;
        float m0 = m[0], m1 = m[1], m2 = m[2];
        // einsum sum order j=0..2, then + t  (exact rn ops, no contraction)
        float c0 = __fadd_rn(__fadd_rn(__fmul_rn(Rb[0], m0), __fmul_rn(Rb[1], m1)), __fmul_rn(Rb[2], m2));
        float c1 = __fadd_rn(__fadd_rn(__fmul_rn(Rb[3], m0), __fmul_rn(Rb[4], m1)), __fmul_rn(Rb[5], m2));
        float c2 = __fadd_rn(__fadd_rn(__fmul_rn(Rb[6], m0), __fmul_rn(Rb[7], m1)), __fmul_rn(Rb[8], m2));
        c0 = __fadd_rn(c0, t0);
        c1 = __fadd_rn(c1, t1);
        c2 = __fadd_rn(c2, t2);
        float zs = (fabsf(c2) > EPSF) ? c2 : EPSF;
        X[k] = __fadd_rn(__fdiv_rn(__fmul_rn(fx, c0), zs), cx);
        Y[k] = __fadd_rn(__fdiv_rn(__fmul_rn(fy, c1), zs), cy);
        Z[k] = c2;
    }

    // area = (x1-x0)*(y2-y0) - (y1-y0)*(x2-x0)   (reference rounding)
    float area = __fsub_rn(__fmul_rn(__fsub_rn(X[1], X[0]), __fsub_rn(Y[2], Y[0])),
                           __fmul_rn(__fsub_rn(Y[1], Y[0]), __fsub_rn(X[2], X[0])));
    if (!(fabsf(area) > EPSF)) return;                       // invalid -> whole warp exits
    if (!(fminf(Z[0], fminf(Z[1], Z[2])) > EPSF)) return;

    float iz0 = __fdiv_rn(Z[0], area);
    float iz1 = __fdiv_rn(Z[1], area);
    float iz2 = __fdiv_rn(Z[2], area);

    float4 e0 = make_float4(__fsub_rn(X[2], X[1]), __fsub_rn(Y[2], Y[1]), X[1], Y[1]);
    float4 e1 = make_float4(__fsub_rn(X[0], X[2]), __fsub_rn(Y[0], Y[2]), X[2], Y[2]);
    float4 e2 = make_float4(__fsub_rn(X[1], X[0]), __fsub_rn(Y[1], Y[0]), X[0], Y[0]);
    float4 e3 = make_float4(iz0, iz1, iz2, 0.f);

    // lanes 0-3 each store one float4 of the setup record
    float4* o = &g_tri[((long)b * MAXF + f) * 4];
    if (lane == 0) o[0] = e0;
    else if (lane == 1) o[1] = e1;
    else if (lane == 2) o[2] = e2;
    else if (lane == 3) o[3] = e3;

    float xmin = fminf(X[0], fminf(X[1], X[2]));
    float xmax = fmaxf(X[0], fmaxf(X[1], X[2]));
    float ymin = fminf(Y[0], fminf(Y[1], Y[2]));
    float ymax = fmaxf(Y[0], fmaxf(Y[1], Y[2]));

    // conservative candidate tile range (extra tiles rejected by tests below)
    int tx0 = max(0, (int)floorf((xmin - ((float)TILE_W - 0.5f)) * (1.f / TILE_W)));
    int tx1 = min(ntx - 1, (int)floorf((xmax - 0.5f) * (1.f / TILE_W)) + 1);
    int ty0 = max(0, (int)floorf((ymin - ((float)TILE_H - 0.5f)) * (1.f / TILE_H)));
    int ty1 = min(nty - 1, (int)floorf((ymax - 0.5f) * (1.f / TILE_H)) + 1);
    if (tx1 < tx0 || ty1 < ty0) return;
    int nx = tx1 - tx0 + 1;
    int ntiles = nx * (ty1 - ty0 + 1);

    for (int i = lane; i < ntiles; i += 32) {
        int tilex = tx0 + (i % nx);
        int tiley = ty0 + (i / nx);
        float tminx = (float)(tilex * TILE_W) + 0.5f;
        float tmaxx = (float)(tilex * TILE_W + TILE_W - 1) + 0.5f;
        float tminy = (float)(tiley * TILE_H) + 0.5f;
        float tmaxy = (float)(tiley * TILE_H + TILE_H - 1) + 0.5f;
        // bbox pre-filter (same as before)
        if (xmax >= tminx && xmin <= tmaxx && ymax >= tminy && ymin <= tmaxy) {
            float tcx = 0.5f * (tminx + tmaxx);
            float tcy = 0.5f * (tminy + tmaxy);
            float thx = 0.5f * (tmaxx - tminx);
            float thy = 0.5f * (tmaxy - tminy);
            float mn0, mx0, mn1, mx1, mn2, mx2;
            edge_range(e0.x, e0.y, e0.z, e0.w, tcx, tcy, thx, thy, mn0, mx0);
            edge_range(e1.x, e1.y, e1.z, e1.w, tcx, tcy, thx, thy, mn1, mx1);
            edge_range(e2.x, e2.y, e2.z, e2.w, tcx, tcy, thx, thy, mn2, mx2);
            bool pos_ok = (mx0 >= 0.f) && (mx1 >= 0.f) && (mx2 >= 0.f);
            bool neg_ok = (mn0 <= 0.f) && (mn1 <= 0.f) && (mn2 <= 0.f);
            if (pos_ok || neg_ok) {
                int slot = b * MAXTILES + tiley * ntx + tilex;
                int p = atomicAdd(&g_tilecnt[slot], 1);   // p < F <= CAP always
                g_tilelist[(long)slot * CAP + p] = f;
            }
        }
    }
}

// 8x8 pixel tile per block, 128 threads = 4 warps (exact R9 kernel, measured
// 62.5us). Every warp covers all 64 pixels (2 adjacent px/lane) but processes
// a disjoint quarter of the tile's list (interleaved CH-chunks, per-warp SMEM
// staging). Partial z-mins merge in SMEM then write directly to out.
// Block re-zeroes its tilecnt slot (self-cleaning for graph replay).
__global__ __launch_bounds__(NT_R)
void dr_raster_kernel(float* __restrict__ out, int W, int H, int ntx) {
    __shared__ float4 sdata[NWARPS][CH * 4];
    __shared__ int    sidx[NWARPS][CH];
    __shared__ float  szmin[NWARPS][65];   // [warp][pixel], padded
    __shared__ int    scount;

    int b = blockIdx.z;
    int tile = blockIdx.y * ntx + blockIdx.x;
    int slot = b * MAXTILES + tile;

    int tid  = threadIdx.x;
    int warp = tid >> 5;
    int lane = tid & 31;

    if (tid == 0) {
        scount = g_tilecnt[slot];
        g_tilecnt[slot] = 0;                 // restore zero for next replay
    }
    __syncthreads();
    int count = scount;

    // lane -> 2 adjacent pixels on one row: p0 = 2*lane, p1 = 2*lane+1
    int p0 = lane * 2;
    int prow = p0 >> 3;          // 0..7
    int pcol = p0 & 7;           // 0,2,4,6

    int row  = blockIdx.y * TILE_H + prow;
    int col0 = blockIdx.x * TILE_W + pcol;
    float py  = (float)row + 0.5f;
    float px0 = (float)col0 + 0.5f;
    float px1 = px0 + 1.0f;

    float zmin0 = BIGF, zmin1 = BIGF;

    const int*    list = &g_tilelist[(long)slot * CAP];
    const float4* tri  = &g_tri[(long)b * MAXF * 4];

    // warp w processes chunks w, w+4, w+8, ...
    for (int base = warp * CH; base < count; base += NWARPS * CH) {
        int n = min(CH, count - base);
        if (lane < n) sidx[warp][lane] = list[base + lane];
        __syncwarp();
        for (int i = lane; i < n * 4; i += 32)
            sdata[warp][i] = tri[(long)sidx[warp][i >> 2] * 4 + (i & 3)];
        __syncwarp();

        for (int j = 0; j < n; j++) {
            float4 d0 = sdata[warp][j * 4 + 0];
            float4 d1 = sdata[warp][j * 4 + 1];
            float4 d2 = sdata[warp][j * 4 + 2];
            float4 d3 = sdata[warp][j * 4 + 3];
            // row-shared terms (reference rounding preserved)
            float a0 = __fmul_rn(d0.x, __fsub_rn(py, d0.w));
            float a1 = __fmul_rn(d1.x, __fsub_rn(py, d1.w));
            float a2 = __fmul_rn(d2.x, __fsub_rn(py, d2.w));
            // pixel 0
            {
                float w0 = __fsub_rn(a0, __fmul_rn(d0.y, __fsub_rn(px0, d0.z)));
                float w1 = __fsub_rn(a1, __fmul_rn(d1.y, __fsub_rn(px0, d1.z)));
                float w2 = __fsub_rn(a2, __fmul_rn(d2.y, __fsub_rn(px0, d2.z)));
                float wmn = fminf(fminf(w0, w1), w2);
                float wmx = fmaxf(fmaxf(w0, w1), w2);
                bool inside = (wmn >= 0.f) || (wmx <= 0.f);
                float zi = __fmaf_rn(w0, d3.x, __fmaf_rn(w1, d3.y, __fmul_rn(w2, d3.z)));
                if (inside && zi > EPSF) zmin0 = fminf(zmin0, zi);
            }
            // pixel 1
            {
                float w0 = __fsub_rn(a0, __fmul_rn(d0.y, __fsub_rn(px1, d0.z)));
                float w1 = __fsub_rn(a1, __fmul_rn(d1.y, __fsub_rn(px1, d1.z)));
                float w2 = __fsub_rn(a2, __fmul_rn(d2.y, __fsub_rn(px1, d2.z)));
                float wmn = fminf(fminf(w0, w1), w2);
                float wmx = fmaxf(fmaxf(w0, w1), w2);
                bool inside = (wmn >= 0.f) || (wmx <= 0.f);
                float zi = __fmaf_rn(w0, d3.x, __fmaf_rn(w1, d3.y, __fmul_rn(w2, d3.z)));
                if (inside && zi > EPSF) zmin1 = fminf(zmin1, zi);
            }
        }
        __syncwarp();
    }

    // merge 4 warps' partial minima
    szmin[warp][p0]     = zmin0;
    szmin[warp][p0 + 1] = zmin1;
    __syncthreads();

    if (tid < 64) {
        int p = tid;
        float z = fminf(fminf(szmin[0][p], szmin[1][p]),
                        fminf(szmin[2][p], szmin[3][p]));
        int r = blockIdx.y * TILE_H + (p >> 3);
        int c = blockIdx.x * TILE_W + (p & 7);
        if (r < H && c < W) {
            long off = ((long)b * H + r) * W + c;
            out[off] = (z < 0.5f * BIGF) ? z : -1.f;
        }
    }
}

extern "C" void kernel_launch(void* const* d_in, const int* in_sizes, int n_in,
                              void* d_out, int out_size) {
    const float* mesh    = (const float*)d_in[0];
    const float* Rm      = (const float*)d_in[1];
    const float* tv      = (const float*)d_in[2];
    const float* focal   = (const float*)d_in[3];
    const float* princpt = (const float*)d_in[4];
    const int*   face    = (const int*)  d_in[5];
    float* out = (float*)d_out;

    int B = in_sizes[1] / 9;            // R is (B,3,3)
    int V = in_sizes[0] / (3 * B);      // mesh is (B,V,3)
    int F = in_sizes[5] / 3;            // face is (F,3)
    int HW = out_size / B;              // out is (B,1,H,W)
    int W = (int)(sqrt((double)HW) + 0.5);
    int H = HW / W;
    int ntx = (W + TILE_W - 1) / TILE_W;
    int nty = (H + TILE_H - 1) / TILE_H;

    int nwarp = B * F;                   // one warp per (b,f)
    dr_setup_bin_kernel<<<(nwarp + (NT / 32) - 1) / (NT / 32), NT>>>(
        mesh, Rm, tv, focal, princpt, face, B, V, F, ntx, nty);
    dim3 grid(ntx, nty, B);
    dr_raster_kernel<<<grid, NT_R>>>(out, W, H, ntx);
}

// round 14
// speedup vs baseline: 6.6831x; 1.1226x over previous
#include <cuda_runtime.h>
#include <math.h>

#define EPSF 1e-8f
#define BIGF 1e10f
#define MAXB 8
#define MAXF 4096

#define TILE_W 8
#define TILE_H 8
#define NT_R   128         // raster: 4 warps; each covers all 64 px, 1/4 of list
#define NWARPS 4
#define NT     128         // setup_bin block size (4 warps = 4 faces per block)

#define MAXBL    4         // batches supported by the bin lists
#define MAXTILES 1024      // 32x32 tiles for 256x256 at 8x8
#define CAP      2048      // per-tile list capacity (> F always)
#define CH       32        // per-warp chunk size (raster)

// Scratch (device globals; zero-initialized at load; raster restores zeros
// so every graph replay sees identical state)
__device__ float4 g_tri[MAXB * MAXF * 4];       // e0,e1,e2,iz per triangle (by face id)
__device__ int    g_tilecnt[MAXBL * MAXTILES];
__device__ int    g_tilelist[MAXBL * MAXTILES * CAP];
__device__ float  g_tilez[MAXBL * MAXTILES * CAP];   // conservative z lower bound per entry

// Conservative interval of affine w over a pixel-center rectangle:
// wc at rect center, radius = |ex|*hy + |ey|*hx, padded for fp slop.
__device__ __forceinline__ void edge_range(float ex, float ey, float ax, float ay,
                                           float cx, float cy, float hx, float hy,
                                           float& wmin, float& wmax) {
    float wc = ex * (cy - ay) - ey * (cx - ax);
    float r  = fabsf(ex) * hy + fabsf(ey) * hx;
    float pad = 1e-5f * (fabsf(wc) + r) + 1e-5f;
    wmin = wc - r - pad;
    wmax = wc + r + pad;
}

// Fused setup + bin, ONE WARP PER (batch, face).
// All 32 lanes redundantly compute the projection/edge setup, lanes 0-3 store
// the 4 float4s of g_tri, then the 32 lanes walk the candidate tile range in
// parallel pushing (face id, conservative tile z-lower-bound) into per-tile lists.
__global__ __launch_bounds__(NT)
void dr_setup_bin_kernel(const float* __restrict__ mesh,
                         const float* __restrict__ Rm,
                         const float* __restrict__ tv,
                         const float* __restrict__ focal,
                         const float* __restrict__ princpt,
                         const int*   __restrict__ face,
                         int B, int V, int F, int ntx, int nty) {
    int warp = threadIdx.x >> 5;
    int lane = threadIdx.x & 31;
    int idx = blockIdx.x * (NT / 32) + warp;      // global warp id = (b,f)
    if (idx >= B * F) return;
    int b = idx / F;
    int f = idx - b * F;

    const float* Rb = Rm + b * 9;
    float t0 = tv[b * 3 + 0], t1 = tv[b * 3 + 1], t2 = tv[b * 3 + 2];
    float fx = focal[b * 2 + 0], fy = focal[b * 2 + 1];
    float cx = princpt[b * 2 + 0], cy = princpt[b * 2 + 1];

    float X[3], Y[3], Z[3];
#pragma unroll
    for (int k = 0; k < 3; k++) {
        int v = face[f * 3 + k];
        const float* m = mesh + ((long)b * V + v) * 3;
        float m0 = m[0], m1 = m[1], m2 = m[2];
        // einsum sum order j=0..2, then + t  (exact rn ops, no contraction)
        float c0 = __fadd_rn(__fadd_rn(__fmul_rn(Rb[0], m0), __fmul_rn(Rb[1], m1)), __fmul_rn(Rb[2], m2));
        float c1 = __fadd_rn(__fadd_rn(__fmul_rn(Rb[3], m0), __fmul_rn(Rb[4], m1)), __fmul_rn(Rb[5], m2));
        float c2 = __fadd_rn(__fadd_rn(__fmul_rn(Rb[6], m0), __fmul_rn(Rb[7], m1)), __fmul_rn(Rb[8], m2));
        c0 = __fadd_rn(c0, t0);
        c1 = __fadd_rn(c1, t1);
        c2 = __fadd_rn(c2, t2);
        float zs = (fabsf(c2) > EPSF) ? c2 : EPSF;
        X[k] = __fadd_rn(__fdiv_rn(__fmul_rn(fx, c0), zs), cx);
        Y[k] = __fadd_rn(__fdiv_rn(__fmul_rn(fy, c1), zs), cy);
        Z[k] = c2;
    }

    // area = (x1-x0)*(y2-y0) - (y1-y0)*(x2-x0)   (reference rounding)
    float area = __fsub_rn(__fmul_rn(__fsub_rn(X[1], X[0]), __fsub_rn(Y[2], Y[0])),
                           __fmul_rn(__fsub_rn(Y[1], Y[0]), __fsub_rn(X[2], X[0])));
    if (!(fabsf(area) > EPSF)) return;                       // invalid -> whole warp exits
    if (!(fminf(Z[0], fminf(Z[1], Z[2])) > EPSF)) return;

    float iz0 = __fdiv_rn(Z[0], area);
    float iz1 = __fdiv_rn(Z[1], area);
    float iz2 = __fdiv_rn(Z[2], area);

    float4 e0 = make_float4(__fsub_rn(X[2], X[1]), __fsub_rn(Y[2], Y[1]), X[1], Y[1]);
    float4 e1 = make_float4(__fsub_rn(X[0], X[2]), __fsub_rn(Y[0], Y[2]), X[2], Y[2]);
    float4 e2 = make_float4(__fsub_rn(X[1], X[0]), __fsub_rn(Y[1], Y[0]), X[0], Y[0]);
    float4 e3 = make_float4(iz0, iz1, iz2, 0.f);

    // lanes 0-3 each store one float4 of the setup record
    float4* o = &g_tri[((long)b * MAXF + f) * 4];
    if (lane == 0) o[0] = e0;
    else if (lane == 1) o[1] = e1;
    else if (lane == 2) o[2] = e2;
    else if (lane == 3) o[3] = e3;

    float xmin = fminf(X[0], fminf(X[1], X[2]));
    float xmax = fmaxf(X[0], fmaxf(X[1], X[2]));
    float ymin = fminf(Y[0], fminf(Y[1], Y[2]));
    float ymax = fmaxf(Y[0], fmaxf(Y[1], Y[2]));

    // per-triangle z gradient (affine zi = w0*iz0 + w1*iz1 + w2*iz2):
    // dzi/dpx = -gx, dzi/dpy = +gy ; radius over an 8x8 tile is constant.
    float gx = e0.y * iz0 + e1.y * iz1 + e2.y * iz2;
    float gy = e0.x * iz0 + e1.x * iz1 + e2.x * iz2;
    float rz = fabsf(gx) * 3.5f + fabsf(gy) * 3.5f;

    // conservative candidate tile range (extra tiles rejected by tests below)
    int tx0 = max(0, (int)floorf((xmin - ((float)TILE_W - 0.5f)) * (1.f / TILE_W)));
    int tx1 = min(ntx - 1, (int)floorf((xmax - 0.5f) * (1.f / TILE_W)) + 1);
    int ty0 = max(0, (int)floorf((ymin - ((float)TILE_H - 0.5f)) * (1.f / TILE_H)));
    int ty1 = min(nty - 1, (int)floorf((ymax - 0.5f) * (1.f / TILE_H)) + 1);
    if (tx1 < tx0 || ty1 < ty0) return;
    int nx = tx1 - tx0 + 1;
    int ntiles = nx * (ty1 - ty0 + 1);

    for (int i = lane; i < ntiles; i += 32) {
        int tilex = tx0 + (i % nx);
        int tiley = ty0 + (i / nx);
        float tminx = (float)(tilex * TILE_W) + 0.5f;
        float tmaxx = (float)(tilex * TILE_W + TILE_W - 1) + 0.5f;
        float tminy = (float)(tiley * TILE_H) + 0.5f;
        float tmaxy = (float)(tiley * TILE_H + TILE_H - 1) + 0.5f;
        // bbox pre-filter (same as before)
        if (xmax >= tminx && xmin <= tmaxx && ymax >= tminy && ymin <= tmaxy) {
            float tcx = 0.5f * (tminx + tmaxx);
            float tcy = 0.5f * (tminy + tmaxy);
            float thx = 0.5f * (tmaxx - tminx);
            float thy = 0.5f * (tmaxy - tminy);
            float mn0, mx0, mn1, mx1, mn2, mx2;
            edge_range(e0.x, e0.y, e0.z, e0.w, tcx, tcy, thx, thy, mn0, mx0);
            edge_range(e1.x, e1.y, e1.z, e1.w, tcx, tcy, thx, thy, mn1, mx1);
            edge_range(e2.x, e2.y, e2.z, e2.w, tcx, tcy, thx, thy, mn2, mx2);
            bool pos_ok = (mx0 >= 0.f) && (mx1 >= 0.f) && (mx2 >= 0.f);
            bool neg_ok = (mn0 <= 0.f) && (mn1 <= 0.f) && (mn2 <= 0.f);
            if (pos_ok || neg_ok) {
                // conservative lower bound of zi over ALL pixel centers of this
                // tile: center value - radius - pad (pad scales with term
                // magnitudes -> dominates every fp rounding difference).
                float wc0 = e0.x * (tcy - e0.w) - e0.y * (tcx - e0.z);
                float wc1 = e1.x * (tcy - e1.w) - e1.y * (tcx - e1.z);
                float wc2 = e2.x * (tcy - e2.w) - e2.y * (tcx - e2.z);
                float tz0 = wc0 * iz0, tz1 = wc1 * iz1, tz2 = wc2 * iz2;
                float zc = tz0 + tz1 + tz2;
                float pad = 1e-4f * (fabsf(tz0) + fabsf(tz1) + fabsf(tz2) + rz) + 1e-6f;
                float zlo = zc - rz - pad;

                int slot = b * MAXTILES + tiley * ntx + tilex;
                int p = atomicAdd(&g_tilecnt[slot], 1);   // p < F <= CAP always
                g_tilelist[(long)slot * CAP + p] = f;
                g_tilez[(long)slot * CAP + p] = zlo;
            }
        }
    }
}

// 8x8 pixel tile per block, 128 threads = 4 warps. Every warp covers all 64
// pixels (2 adjacent px/lane), processes a disjoint quarter of the tile's list.
// Z-occlusion cull: a triangle whose conservative z lower bound exceeds the
// warp's current max partial z-min provably cannot change any pixel min ->
// warp-uniform skip. Output is bit-identical and order-independent.
__global__ __launch_bounds__(NT_R)
void dr_raster_kernel(float* __restrict__ out, int W, int H, int ntx) {
    __shared__ float4 sdata[NWARPS][CH * 4];
    __shared__ int    sidx[NWARPS][CH];
    __shared__ float  stz[NWARPS][CH];
    __shared__ float  szmin[NWARPS][65];   // [warp][pixel], padded
    __shared__ int    scount;

    int b = blockIdx.z;
    int tile = blockIdx.y * ntx + blockIdx.x;
    int slot = b * MAXTILES + tile;

    int tid  = threadIdx.x;
    int warp = tid >> 5;
    int lane = tid & 31;

    if (tid == 0) {
        scount = g_tilecnt[slot];
        g_tilecnt[slot] = 0;                 // restore zero for next replay
    }
    __syncthreads();
    int count = scount;

    // lane -> 2 adjacent pixels on one row: p0 = 2*lane, p1 = 2*lane+1
    int p0 = lane * 2;
    int prow = p0 >> 3;          // 0..7
    int pcol = p0 & 7;           // 0,2,4,6

    int row  = blockIdx.y * TILE_H + prow;
    int col0 = blockIdx.x * TILE_W + pcol;
    float py  = (float)row + 0.5f;
    float px0 = (float)col0 + 0.5f;
    float px1 = px0 + 1.0f;

    float zmin0 = BIGF, zmin1 = BIGF;
    float wzmax = BIGF;

    const int*    list  = &g_tilelist[(long)slot * CAP];
    const float*  zlist = &g_tilez[(long)slot * CAP];
    const float4* tri   = &g_tri[(long)b * MAXF * 4];

    // warp w processes chunks w, w+4, w+8, ...
    for (int base = warp * CH; base < count; base += NWARPS * CH) {
        int n = min(CH, count - base);
        if (lane < n) {
            sidx[warp][lane] = list[base + lane];
            stz[warp][lane]  = zlist[base + lane];
        }
        __syncwarp();
        for (int i = lane; i < n * 4; i += 32)
            sdata[warp][i] = tri[(long)sidx[warp][i >> 2] * 4 + (i & 3)];
        __syncwarp();

        for (int j = 0; j < n; j++) {
            if ((j & 7) == 0) {
                // refresh warp-wide max of current partial z-mins
                float m = fmaxf(zmin0, zmin1);
#pragma unroll
                for (int off = 16; off; off >>= 1)
                    m = fmaxf(m, __shfl_xor_sync(0xffffffffu, m, off));
                wzmax = m;
            }
            // z-occlusion: cannot lower any pixel min -> skip (warp-uniform)
            if (stz[warp][j] > wzmax) continue;

            float4 d0 = sdata[warp][j * 4 + 0];
            float4 d1 = sdata[warp][j * 4 + 1];
            float4 d2 = sdata[warp][j * 4 + 2];
            float4 d3 = sdata[warp][j * 4 + 3];
            // row-shared terms (reference rounding preserved)
            float a0 = __fmul_rn(d0.x, __fsub_rn(py, d0.w));
            float a1 = __fmul_rn(d1.x, __fsub_rn(py, d1.w));
            float a2 = __fmul_rn(d2.x, __fsub_rn(py, d2.w));
            // pixel 0
            {
                float w0 = __fsub_rn(a0, __fmul_rn(d0.y, __fsub_rn(px0, d0.z)));
                float w1 = __fsub_rn(a1, __fmul_rn(d1.y, __fsub_rn(px0, d1.z)));
                float w2 = __fsub_rn(a2, __fmul_rn(d2.y, __fsub_rn(px0, d2.z)));
                float wmn = fminf(fminf(w0, w1), w2);
                float wmx = fmaxf(fmaxf(w0, w1), w2);
                bool inside = (wmn >= 0.f) || (wmx <= 0.f);
                float zi = __fmaf_rn(w0, d3.x, __fmaf_rn(w1, d3.y, __fmul_rn(w2, d3.z)));
                if (inside && zi > EPSF) zmin0 = fminf(zmin0, zi);
            }
            // pixel 1
            {
                float w0 = __fsub_rn(a0, __fmul_rn(d0.y, __fsub_rn(px1, d0.z)));
                float w1 = __fsub_rn(a1, __fmul_rn(d1.y, __fsub_rn(px1, d1.z)));
                float w2 = __fsub_rn(a2, __fmul_rn(d2.y, __fsub_rn(px1, d2.z)));
                float wmn = fminf(fminf(w0, w1), w2);
                float wmx = fmaxf(fmaxf(w0, w1), w2);
                bool inside = (wmn >= 0.f) || (wmx <= 0.f);
                float zi = __fmaf_rn(w0, d3.x, __fmaf_rn(w1, d3.y, __fmul_rn(w2, d3.z)));
                if (inside && zi > EPSF) zmin1 = fminf(zmin1, zi);
            }
        }
        __syncwarp();
    }

    // merge 4 warps' partial minima
    szmin[warp][p0]     = zmin0;
    szmin[warp][p0 + 1] = zmin1;
    __syncthreads();

    if (tid < 64) {
        int p = tid;
        float z = fminf(fminf(szmin[0][p], szmin[1][p]),
                        fminf(szmin[2][p], szmin[3][p]));
        int r = blockIdx.y * TILE_H + (p >> 3);
        int c = blockIdx.x * TILE_W + (p & 7);
        if (r < H && c < W) {
            long off = ((long)b * H + r) * W + c;
            out[off] = (z < 0.5f * BIGF) ? z : -1.f;
        }
    }
}

extern "C" void kernel_launch(void* const* d_in, const int* in_sizes, int n_in,
                              void* d_out, int out_size) {
    const float* mesh    = (const float*)d_in[0];
    const float* Rm      = (const float*)d_in[1];
    const float* tv      = (const float*)d_in[2];
    const float* focal   = (const float*)d_in[3];
    const float* princpt = (const float*)d_in[4];
    const int*   face    = (const int*)  d_in[5];
    float* out = (float*)d_out;

    int B = in_sizes[1] / 9;            // R is (B,3,3)
    int V = in_sizes[0] / (3 * B);      // mesh is (B,V,3)
    int F = in_sizes[5] / 3;            // face is (F,3)
    int HW = out_size / B;              // out is (B,1,H,W)
    int W = (int)(sqrt((double)HW) + 0.5);
    int H = HW / W;
    int ntx = (W + TILE_W - 1) / TILE_W;
    int nty = (H + TILE_H - 1) / TILE_H;

    int nwarp = B * F;                   // one warp per (b,f)
    dr_setup_bin_kernel<<<(nwarp + (NT / 32) - 1) / (NT / 32), NT>>>(
        mesh, Rm, tv, focal, princpt, face, B, V, F, ntx, nty);
    dim3 grid(ntx, nty, B);
    dr_raster_kernel<<<grid, NT_R>>>(out, W, H, ntx);
}

// round 15
// speedup vs baseline: 6.8546x; 1.0257x over previous
#include <cuda_runtime.h>
#include <math.h>

#define EPSF 1e-8f
#define BIGF 1e10f
#define MAXB 8
#define MAXF 4096

#define TILE_W 8
#define TILE_H 8
#define NT_R   128         // raster: 4 warps; each covers all 64 px, 1/4 of list
#define NWARPS 4
#define NT     128         // setup_bin block size (4 warps = 4 faces per block)

#define MAXBL    4         // batches supported by the bin lists
#define MAXTILES 1024      // 32x32 tiles for 256x256 at 8x8
#define CAP      2048      // per-tile list capacity (> F always)
#define CH       32        // per-warp chunk size (raster)

// Scratch (device globals; zero-initialized at load; raster restores zeros
// so every graph replay sees identical state)
__device__ float4 g_tri[MAXB * MAXF * 4];       // e0,e1,e2,iz per triangle (by face id)
__device__ int    g_tilecnt[MAXBL * MAXTILES];
__device__ int    g_tilelist[MAXBL * MAXTILES * CAP];
__device__ float  g_tilez[MAXBL * MAXTILES * CAP];   // conservative z lower bound per entry

// Conservative interval of affine w over a pixel-center rectangle:
// wc at rect center, radius = |ex|*hy + |ey|*hx, padded for fp slop.
__device__ __forceinline__ void edge_range(float ex, float ey, float ax, float ay,
                                           float cx, float cy, float hx, float hy,
                                           float& wmin, float& wmax) {
    float wc = ex * (cy - ay) - ey * (cx - ax);
    float r  = fabsf(ex) * hy + fabsf(ey) * hx;
    float pad = 1e-5f * (fabsf(wc) + r) + 1e-5f;
    wmin = wc - r - pad;
    wmax = wc + r + pad;
}

// Fused setup + bin, ONE WARP PER (batch, face).
// All 32 lanes redundantly compute the projection/edge setup, lanes 0-3 store
// the 4 float4s of g_tri, then the 32 lanes walk the candidate tile range in
// parallel pushing (face id, conservative tile z-lower-bound) into per-tile lists.
__global__ __launch_bounds__(NT)
void dr_setup_bin_kernel(const float* __restrict__ mesh,
                         const float* __restrict__ Rm,
                         const float* __restrict__ tv,
                         const float* __restrict__ focal,
                         const float* __restrict__ princpt,
                         const int*   __restrict__ face,
                         int B, int V, int F, int ntx, int nty) {
    int warp = threadIdx.x >> 5;
    int lane = threadIdx.x & 31;
    int idx = blockIdx.x * (NT / 32) + warp;      // global warp id = (b,f)
    if (idx >= B * F) return;
    int b = idx / F;
    int f = idx - b * F;

    const float* Rb = Rm + b * 9;
    float t0 = tv[b * 3 + 0], t1 = tv[b * 3 + 1], t2 = tv[b * 3 + 2];
    float fx = focal[b * 2 + 0], fy = focal[b * 2 + 1];
    float cx = princpt[b * 2 + 0], cy = princpt[b * 2 + 1];

    float X[3], Y[3], Z[3];
#pragma unroll
    for (int k = 0; k < 3; k++) {
        int v = face[f * 3 + k];
        const float* m = mesh + ((long)b * V + v) * 3;
        float m0 = m[0], m1 = m[1], m2 = m[2];
        // einsum sum order j=0..2, then + t  (exact rn ops, no contraction)
        float c0 = __fadd_rn(__fadd_rn(__fmul_rn(Rb[0], m0), __fmul_rn(Rb[1], m1)), __fmul_rn(Rb[2], m2));
        float c1 = __fadd_rn(__fadd_rn(__fmul_rn(Rb[3], m0), __fmul_rn(Rb[4], m1)), __fmul_rn(Rb[5], m2));
        float c2 = __fadd_rn(__fadd_rn(__fmul_rn(Rb[6], m0), __fmul_rn(Rb[7], m1)), __fmul_rn(Rb[8], m2));
        c0 = __fadd_rn(c0, t0);
        c1 = __fadd_rn(c1, t1);
        c2 = __fadd_rn(c2, t2);
        float zs = (fabsf(c2) > EPSF) ? c2 : EPSF;
        X[k] = __fadd_rn(__fdiv_rn(__fmul_rn(fx, c0), zs), cx);
        Y[k] = __fadd_rn(__fdiv_rn(__fmul_rn(fy, c1), zs), cy);
        Z[k] = c2;
    }

    // area = (x1-x0)*(y2-y0) - (y1-y0)*(x2-x0)   (reference rounding)
    float area = __fsub_rn(__fmul_rn(__fsub_rn(X[1], X[0]), __fsub_rn(Y[2], Y[0])),
                           __fmul_rn(__fsub_rn(Y[1], Y[0]), __fsub_rn(X[2], X[0])));
    if (!(fabsf(area) > EPSF)) return;                       // invalid -> whole warp exits
    if (!(fminf(Z[0], fminf(Z[1], Z[2])) > EPSF)) return;

    float iz0 = __fdiv_rn(Z[0], area);
    float iz1 = __fdiv_rn(Z[1], area);
    float iz2 = __fdiv_rn(Z[2], area);

    float4 e0 = make_float4(__fsub_rn(X[2], X[1]), __fsub_rn(Y[2], Y[1]), X[1], Y[1]);
    float4 e1 = make_float4(__fsub_rn(X[0], X[2]), __fsub_rn(Y[0], Y[2]), X[2], Y[2]);
    float4 e2 = make_float4(__fsub_rn(X[1], X[0]), __fsub_rn(Y[1], Y[0]), X[0], Y[0]);
    float4 e3 = make_float4(iz0, iz1, iz2, 0.f);

    // lanes 0-3 each store one float4 of the setup record
    float4* o = &g_tri[((long)b * MAXF + f) * 4];
    if (lane == 0) o[0] = e0;
    else if (lane == 1) o[1] = e1;
    else if (lane == 2) o[2] = e2;
    else if (lane == 3) o[3] = e3;

    float xmin = fminf(X[0], fminf(X[1], X[2]));
    float xmax = fmaxf(X[0], fmaxf(X[1], X[2]));
    float ymin = fminf(Y[0], fminf(Y[1], Y[2]));
    float ymax = fmaxf(Y[0], fmaxf(Y[1], Y[2]));

    // per-triangle z gradient (affine zi = w0*iz0 + w1*iz1 + w2*iz2):
    // dzi/dpx = -gx, dzi/dpy = +gy ; radius over an 8x8 tile is constant.
    float gx = e0.y * iz0 + e1.y * iz1 + e2.y * iz2;
    float gy = e0.x * iz0 + e1.x * iz1 + e2.x * iz2;
    float rz = fabsf(gx) * 3.5f + fabsf(gy) * 3.5f;

    // conservative candidate tile range (extra tiles rejected by tests below)
    int tx0 = max(0, (int)floorf((xmin - ((float)TILE_W - 0.5f)) * (1.f / TILE_W)));
    int tx1 = min(ntx - 1, (int)floorf((xmax - 0.5f) * (1.f / TILE_W)) + 1);
    int ty0 = max(0, (int)floorf((ymin - ((float)TILE_H - 0.5f)) * (1.f / TILE_H)));
    int ty1 = min(nty - 1, (int)floorf((ymax - 0.5f) * (1.f / TILE_H)) + 1);
    if (tx1 < tx0 || ty1 < ty0) return;
    int nx = tx1 - tx0 + 1;
    int ntiles = nx * (ty1 - ty0 + 1);

    for (int i = lane; i < ntiles; i += 32) {
        int tilex = tx0 + (i % nx);
        int tiley = ty0 + (i / nx);
        float tminx = (float)(tilex * TILE_W) + 0.5f;
        float tmaxx = (float)(tilex * TILE_W + TILE_W - 1) + 0.5f;
        float tminy = (float)(tiley * TILE_H) + 0.5f;
        float tmaxy = (float)(tiley * TILE_H + TILE_H - 1) + 0.5f;
        // bbox pre-filter (same as before)
        if (xmax >= tminx && xmin <= tmaxx && ymax >= tminy && ymin <= tmaxy) {
            float tcx = 0.5f * (tminx + tmaxx);
            float tcy = 0.5f * (tminy + tmaxy);
            float thx = 0.5f * (tmaxx - tminx);
            float thy = 0.5f * (tmaxy - tminy);
            float mn0, mx0, mn1, mx1, mn2, mx2;
            edge_range(e0.x, e0.y, e0.z, e0.w, tcx, tcy, thx, thy, mn0, mx0);
            edge_range(e1.x, e1.y, e1.z, e1.w, tcx, tcy, thx, thy, mn1, mx1);
            edge_range(e2.x, e2.y, e2.z, e2.w, tcx, tcy, thx, thy, mn2, mx2);
            bool pos_ok = (mx0 >= 0.f) && (mx1 >= 0.f) && (mx2 >= 0.f);
            bool neg_ok = (mn0 <= 0.f) && (mn1 <= 0.f) && (mn2 <= 0.f);
            if (pos_ok || neg_ok) {
                // conservative lower bound of zi over ALL pixel centers of this
                // tile: center value - radius - pad (pad scales with term
                // magnitudes -> dominates every fp rounding difference).
                float wc0 = e0.x * (tcy - e0.w) - e0.y * (tcx - e0.z);
                float wc1 = e1.x * (tcy - e1.w) - e1.y * (tcx - e1.z);
                float wc2 = e2.x * (tcy - e2.w) - e2.y * (tcx - e2.z);
                float tz0 = wc0 * iz0, tz1 = wc1 * iz1, tz2 = wc2 * iz2;
                float zc = tz0 + tz1 + tz2;
                float pad = 1e-4f * (fabsf(tz0) + fabsf(tz1) + fabsf(tz2) + rz) + 1e-6f;
                float zlo = zc - rz - pad;

                int slot = b * MAXTILES + tiley * ntx + tilex;
                int p = atomicAdd(&g_tilecnt[slot], 1);   // p < F <= CAP always
                g_tilelist[(long)slot * CAP + p] = f;
                g_tilez[(long)slot * CAP + p] = zlo;
            }
        }
    }
}

// 8x8 pixel tile per block, 128 threads = 4 warps. Every warp covers all 64
// pixels (2 adjacent px/lane), processes a disjoint quarter of the tile's list.
// Z-occlusion cull BEFORE staging: per chunk, each lane tests its entry's
// conservative z lower bound against the warp's max partial z-min (refreshed
// at chunk start; z-mins only decrease so the bound stays valid -> skips are
// provably output-neutral). Survivors are ballot-compacted; only their data
// is staged; inner loop is branch-free. Partial z-mins merge in SMEM.
__global__ __launch_bounds__(NT_R)
void dr_raster_kernel(float* __restrict__ out, int W, int H, int ntx) {
    __shared__ float4 sdata[NWARPS][CH * 4];
    __shared__ int    sidx[NWARPS][CH];
    __shared__ float  szmin[NWARPS][65];   // [warp][pixel], padded
    __shared__ int    scount;

    int b = blockIdx.z;
    int tile = blockIdx.y * ntx + blockIdx.x;
    int slot = b * MAXTILES + tile;

    int tid  = threadIdx.x;
    int warp = tid >> 5;
    int lane = tid & 31;

    if (tid == 0) {
        scount = g_tilecnt[slot];
        g_tilecnt[slot] = 0;                 // restore zero for next replay
    }
    __syncthreads();
    int count = scount;

    // lane -> 2 adjacent pixels on one row: p0 = 2*lane, p1 = 2*lane+1
    int p0 = lane * 2;
    int prow = p0 >> 3;          // 0..7
    int pcol = p0 & 7;           // 0,2,4,6

    int row  = blockIdx.y * TILE_H + prow;
    int col0 = blockIdx.x * TILE_W + pcol;
    float py  = (float)row + 0.5f;
    float px0 = (float)col0 + 0.5f;
    float px1 = px0 + 1.0f;

    float zmin0 = BIGF, zmin1 = BIGF;

    const int*    list  = &g_tilelist[(long)slot * CAP];
    const float*  zlist = &g_tilez[(long)slot * CAP];
    const float4* tri   = &g_tri[(long)b * MAXF * 4];

    // warp w processes chunks w, w+4, w+8, ...  (CH == 32: one entry per lane)
    for (int base = warp * CH; base < count; base += NWARPS * CH) {
        int n = min(CH, count - base);

        // refresh warp-wide max of current partial z-mins (only decreases)
        float wzmax = fmaxf(zmin0, zmin1);
#pragma unroll
        for (int off = 16; off; off >>= 1)
            wzmax = fmaxf(wzmax, __shfl_xor_sync(0xffffffffu, wzmax, off));

        // z-cull + ballot compaction before staging
        bool keep = false;
        int fid = 0;
        if (lane < n) {
            fid = list[base + lane];
            keep = (zlist[base + lane] <= wzmax);
        }
        unsigned bal = __ballot_sync(0xffffffffu, keep);
        int nsurv = __popc(bal);
        if (keep) {
            int pos = __popc(bal & ((1u << lane) - 1u));
            sidx[warp][pos] = fid;
        }
        __syncwarp();
        if (nsurv == 0) continue;

        // stage only survivors' triangle data (4 float4 per entry)
        for (int i = lane; i < nsurv * 4; i += 32)
            sdata[warp][i] = tri[(long)sidx[warp][i >> 2] * 4 + (i & 3)];
        __syncwarp();

        for (int j = 0; j < nsurv; j++) {
            float4 d0 = sdata[warp][j * 4 + 0];
            float4 d1 = sdata[warp][j * 4 + 1];
            float4 d2 = sdata[warp][j * 4 + 2];
            float4 d3 = sdata[warp][j * 4 + 3];
            // row-shared terms (reference rounding preserved)
            float a0 = __fmul_rn(d0.x, __fsub_rn(py, d0.w));
            float a1 = __fmul_rn(d1.x, __fsub_rn(py, d1.w));
            float a2 = __fmul_rn(d2.x, __fsub_rn(py, d2.w));
            // pixel 0
            {
                float w0 = __fsub_rn(a0, __fmul_rn(d0.y, __fsub_rn(px0, d0.z)));
                float w1 = __fsub_rn(a1, __fmul_rn(d1.y, __fsub_rn(px0, d1.z)));
                float w2 = __fsub_rn(a2, __fmul_rn(d2.y, __fsub_rn(px0, d2.z)));
                float wmn = fminf(fminf(w0, w1), w2);
                float wmx = fmaxf(fmaxf(w0, w1), w2);
                bool inside = (wmn >= 0.f) || (wmx <= 0.f);
                float zi = __fmaf_rn(w0, d3.x, __fmaf_rn(w1, d3.y, __fmul_rn(w2, d3.z)));
                if (inside && zi > EPSF) zmin0 = fminf(zmin0, zi);
            }
            // pixel 1
            {
                float w0 = __fsub_rn(a0, __fmul_rn(d0.y, __fsub_rn(px1, d0.z)));
                float w1 = __fsub_rn(a1, __fmul_rn(d1.y, __fsub_rn(px1, d1.z)));
                float w2 = __fsub_rn(a2, __fmul_rn(d2.y, __fsub_rn(px1, d2.z)));
                float wmn = fminf(fminf(w0, w1), w2);
                float wmx = fmaxf(fmaxf(w0, w1), w2);
                bool inside = (wmn >= 0.f) || (wmx <= 0.f);
                float zi = __fmaf_rn(w0, d3.x, __fmaf_rn(w1, d3.y, __fmul_rn(w2, d3.z)));
                if (inside && zi > EPSF) zmin1 = fminf(zmin1, zi);
            }
        }
        __syncwarp();
    }

    // merge 4 warps' partial minima
    szmin[warp][p0]     = zmin0;
    szmin[warp][p0 + 1] = zmin1;
    __syncthreads();

    if (tid < 64) {
        int p = tid;
        float z = fminf(fminf(szmin[0][p], szmin[1][p]),
                        fminf(szmin[2][p], szmin[3][p]));
        int r = blockIdx.y * TILE_H + (p >> 3);
        int c = blockIdx.x * TILE_W + (p & 7);
        if (r < H && c < W) {
            long off = ((long)b * H + r) * W + c;
            out[off] = (z < 0.5f * BIGF) ? z : -1.f;
        }
    }
}

extern "C" void kernel_launch(void* const* d_in, const int* in_sizes, int n_in,
                              void* d_out, int out_size) {
    const float* mesh    = (const float*)d_in[0];
    const float* Rm      = (const float*)d_in[1];
    const float* tv      = (const float*)d_in[2];
    const float* focal   = (const float*)d_in[3];
    const float* princpt = (const float*)d_in[4];
    const int*   face    = (const int*)  d_in[5];
    float* out = (float*)d_out;

    int B = in_sizes[1] / 9;            // R is (B,3,3)
    int V = in_sizes[0] / (3 * B);      // mesh is (B,V,3)
    int F = in_sizes[5] / 3;            // face is (F,3)
    int HW = out_size / B;              // out is (B,1,H,W)
    int W = (int)(sqrt((double)HW) + 0.5);
    int H = HW / W;
    int ntx = (W + TILE_W - 1) / TILE_W;
    int nty = (H + TILE_H - 1) / TILE_H;

    int nwarp = B * F;                   // one warp per (b,f)
    dr_setup_bin_kernel<<<(nwarp + (NT / 32) - 1) / (NT / 32), NT>>>(
        mesh, Rm, tv, focal, princpt, face, B, V, F, ntx, nty);
    dim3 grid(ntx, nty, B);
    dr_raster_kernel<<<grid, NT_R>>>(out, W, H, ntx);
}

// round 16
// speedup vs baseline: 7.6960x; 1.1228x over previous
#include <cuda_runtime.h>
#include <math.h>

#define EPSF 1e-8f
#define BIGF 1e10f
#define MAXB 8
#define MAXF 4096

#define TILE_W 8
#define TILE_H 8
#define NT_R   128         // raster: 4 warps; each covers all 64 px, 1/4 of list
#define NWARPS 4
#define NT     128         // setup_bin block size (4 warps = 4 faces per block)

#define MAXBL    4         // batches supported by the bin lists
#define MAXTILES 1024      // 32x32 tiles for 256x256 at 8x8
#define CAP      2048      // per-tile list capacity (> F always)
#define CH       32        // per-warp chunk size (raster)

#define ZMASK  0xFFFFF800u   // top 21 bits: truncated positive-float zlo
#define FMASK  0x000007FFu   // bottom 11 bits: face id (F < 2048)

// Scratch (device globals; zero-initialized at load; raster restores zeros
// so every graph replay sees identical state)
__device__ float4 g_tri[MAXB * MAXF * 4];       // e0,e1,e2,iz per triangle (by face id)
__device__ int    g_tilecnt[MAXBL * MAXTILES];
__device__ unsigned g_tilelist[MAXBL * MAXTILES * CAP];  // packed (zlo21 | fid11)

// Conservative interval of affine w over a pixel-center rectangle:
// wc at rect center, radius = |ex|*hy + |ey|*hx, padded for fp slop.
__device__ __forceinline__ void edge_range(float ex, float ey, float ax, float ay,
                                           float cx, float cy, float hx, float hy,
                                           float& wmin, float& wmax) {
    float wc = ex * (cy - ay) - ey * (cx - ax);
    float r  = fabsf(ex) * hy + fabsf(ey) * hx;
    float pad = 1e-5f * (fabsf(wc) + r) + 1e-5f;
    wmin = wc - r - pad;
    wmax = wc + r + pad;
}

// Fused setup + bin, ONE WARP PER (batch, face).
// All 32 lanes redundantly compute the projection/edge setup, lanes 0-3 store
// the 4 float4s of g_tri, then the 32 lanes walk the candidate tile range in
// parallel pushing packed (zlo | face id) entries into per-tile lists.
__global__ __launch_bounds__(NT)
void dr_setup_bin_kernel(const float* __restrict__ mesh,
                         const float* __restrict__ Rm,
                         const float* __restrict__ tv,
                         const float* __restrict__ focal,
                         const float* __restrict__ princpt,
                         const int*   __restrict__ face,
                         int B, int V, int F, int ntx, int nty) {
    int warp = threadIdx.x >> 5;
    int lane = threadIdx.x & 31;
    int idx = blockIdx.x * (NT / 32) + warp;      // global warp id = (b,f)
    if (idx >= B * F) return;
    int b = idx / F;
    int f = idx - b * F;

    const float* Rb = Rm + b * 9;
    float t0 = tv[b * 3 + 0], t1 = tv[b * 3 + 1], t2 = tv[b * 3 + 2];
    float fx = focal[b * 2 + 0], fy = focal[b * 2 + 1];
    float cx = princpt[b * 2 + 0], cy = princpt[b * 2 + 1];

    float X[3], Y[3], Z[3];
#pragma unroll
    for (int k = 0; k < 3; k++) {
        int v = face[f * 3 + k];
        const float* m = mesh + ((long)b * V + v) * 3;
        float m0 = m[0], m1 = m[1], m2 = m[2];
        // einsum sum order j=0..2, then + t  (exact rn ops, no contraction)
        float c0 = __fadd_rn(__fadd_rn(__fmul_rn(Rb[0], m0), __fmul_rn(Rb[1], m1)), __fmul_rn(Rb[2], m2));
        float c1 = __fadd_rn(__fadd_rn(__fmul_rn(Rb[3], m0), __fmul_rn(Rb[4], m1)), __fmul_rn(Rb[5], m2));
        float c2 = __fadd_rn(__fadd_rn(__fmul_rn(Rb[6], m0), __fmul_rn(Rb[7], m1)), __fmul_rn(Rb[8], m2));
        c0 = __fadd_rn(c0, t0);
        c1 = __fadd_rn(c1, t1);
        c2 = __fadd_rn(c2, t2);
        float zs = (fabsf(c2) > EPSF) ? c2 : EPSF;
        X[k] = __fadd_rn(__fdiv_rn(__fmul_rn(fx, c0), zs), cx);
        Y[k] = __fadd_rn(__fdiv_rn(__fmul_rn(fy, c1), zs), cy);
        Z[k] = c2;
    }

    // area = (x1-x0)*(y2-y0) - (y1-y0)*(x2-x0)   (reference rounding)
    float area = __fsub_rn(__fmul_rn(__fsub_rn(X[1], X[0]), __fsub_rn(Y[2], Y[0])),
                           __fmul_rn(__fsub_rn(Y[1], Y[0]), __fsub_rn(X[2], X[0])));
    if (!(fabsf(area) > EPSF)) return;                       // invalid -> whole warp exits
    if (!(fminf(Z[0], fminf(Z[1], Z[2])) > EPSF)) return;

    float iz0 = __fdiv_rn(Z[0], area);
    float iz1 = __fdiv_rn(Z[1], area);
    float iz2 = __fdiv_rn(Z[2], area);

    float4 e0 = make_float4(__fsub_rn(X[2], X[1]), __fsub_rn(Y[2], Y[1]), X[1], Y[1]);
    float4 e1 = make_float4(__fsub_rn(X[0], X[2]), __fsub_rn(Y[0], Y[2]), X[2], Y[2]);
    float4 e2 = make_float4(__fsub_rn(X[1], X[0]), __fsub_rn(Y[1], Y[0]), X[0], Y[0]);
    float4 e3 = make_float4(iz0, iz1, iz2, 0.f);

    // lanes 0-3 each store one float4 of the setup record
    float4* o = &g_tri[((long)b * MAXF + f) * 4];
    if (lane == 0) o[0] = e0;
    else if (lane == 1) o[1] = e1;
    else if (lane == 2) o[2] = e2;
    else if (lane == 3) o[3] = e3;

    float xmin = fminf(X[0], fminf(X[1], X[2]));
    float xmax = fmaxf(X[0], fmaxf(X[1], X[2]));
    float ymin = fminf(Y[0], fminf(Y[1], Y[2]));
    float ymax = fmaxf(Y[0], fmaxf(Y[1], Y[2]));

    // per-triangle z gradient (affine zi = w0*iz0 + w1*iz1 + w2*iz2):
    // dzi/dpx = -gx, dzi/dpy = +gy ; radius over an 8x8 tile is constant.
    float gx = e0.y * iz0 + e1.y * iz1 + e2.y * iz2;
    float gy = e0.x * iz0 + e1.x * iz1 + e2.x * iz2;
    float rz = fabsf(gx) * 3.5f + fabsf(gy) * 3.5f;

    // conservative candidate tile range (extra tiles rejected by tests below)
    int tx0 = max(0, (int)floorf((xmin - ((float)TILE_W - 0.5f)) * (1.f / TILE_W)));
    int tx1 = min(ntx - 1, (int)floorf((xmax - 0.5f) * (1.f / TILE_W)) + 1);
    int ty0 = max(0, (int)floorf((ymin - ((float)TILE_H - 0.5f)) * (1.f / TILE_H)));
    int ty1 = min(nty - 1, (int)floorf((ymax - 0.5f) * (1.f / TILE_H)) + 1);
    if (tx1 < tx0 || ty1 < ty0) return;
    int nx = tx1 - tx0 + 1;
    int ntiles = nx * (ty1 - ty0 + 1);

    for (int i = lane; i < ntiles; i += 32) {
        int tilex = tx0 + (i % nx);
        int tiley = ty0 + (i / nx);
        float tminx = (float)(tilex * TILE_W) + 0.5f;
        float tmaxx = (float)(tilex * TILE_W + TILE_W - 1) + 0.5f;
        float tminy = (float)(tiley * TILE_H) + 0.5f;
        float tmaxy = (float)(tiley * TILE_H + TILE_H - 1) + 0.5f;
        // bbox pre-filter (same as before)
        if (xmax >= tminx && xmin <= tmaxx && ymax >= tminy && ymin <= tmaxy) {
            float tcx = 0.5f * (tminx + tmaxx);
            float tcy = 0.5f * (tminy + tmaxy);
            float thx = 0.5f * (tmaxx - tminx);
            float thy = 0.5f * (tmaxy - tminy);
            float mn0, mx0, mn1, mx1, mn2, mx2;
            edge_range(e0.x, e0.y, e0.z, e0.w, tcx, tcy, thx, thy, mn0, mx0);
            edge_range(e1.x, e1.y, e1.z, e1.w, tcx, tcy, thx, thy, mn1, mx1);
            edge_range(e2.x, e2.y, e2.z, e2.w, tcx, tcy, thx, thy, mn2, mx2);
            bool pos_ok = (mx0 >= 0.f) && (mx1 >= 0.f) && (mx2 >= 0.f);
            bool neg_ok = (mn0 <= 0.f) && (mn1 <= 0.f) && (mn2 <= 0.f);
            if (pos_ok || neg_ok) {
                // conservative lower bound of zi over ALL pixel centers of this
                // tile: center value - radius - pad; clamped to 0 (still a valid
                // bound for contributing zi > EPSF) so float bits are monotone.
                float wc0 = e0.x * (tcy - e0.w) - e0.y * (tcx - e0.z);
                float wc1 = e1.x * (tcy - e1.w) - e1.y * (tcx - e1.z);
                float wc2 = e2.x * (tcy - e2.w) - e2.y * (tcx - e2.z);
                float tz0 = wc0 * iz0, tz1 = wc1 * iz1, tz2 = wc2 * iz2;
                float zc = tz0 + tz1 + tz2;
                float pad = 1e-4f * (fabsf(tz0) + fabsf(tz1) + fabsf(tz2) + rz) + 1e-6f;
                float zlo = fmaxf(zc - rz - pad, 0.f);
                // truncate down to 21 bits (positive float: smaller bits ->
                // smaller value -> still a lower bound), pack face id in low 11
                unsigned entry = (__float_as_uint(zlo) & ZMASK) | (unsigned)f;

                int slot = b * MAXTILES + tiley * ntx + tilex;
                int p = atomicAdd(&g_tilecnt[slot], 1);   // p < F <= CAP always
                g_tilelist[(long)slot * CAP + p] = entry;
            }
        }
    }
}

// 8x8 pixel tile per block, 128 threads = 4 warps. Every warp covers all 64
// pixels (2 adjacent px/lane), processes a disjoint quarter of the tile's list.
// Z-occlusion cull BEFORE staging, from a SINGLE packed load: entry = top-21
// bits truncated zlo + 11-bit face id. Skip when zlo_dec > warp-max partial
// z-min (z-mins only decrease -> provably output-neutral). Survivors are
// ballot-compacted; only their data is staged; inner loop branch-free.
__global__ __launch_bounds__(NT_R)
void dr_raster_kernel(float* __restrict__ out, int W, int H, int ntx) {
    __shared__ float4 sdata[NWARPS][CH * 4];
    __shared__ int    sidx[NWARPS][CH];
    __shared__ float  szmin[NWARPS][65];   // [warp][pixel], padded
    __shared__ int    scount;

    int b = blockIdx.z;
    int tile = blockIdx.y * ntx + blockIdx.x;
    int slot = b * MAXTILES + tile;

    int tid  = threadIdx.x;
    int warp = tid >> 5;
    int lane = tid & 31;

    if (tid == 0) {
        scount = g_tilecnt[slot];
        g_tilecnt[slot] = 0;                 // restore zero for next replay
    }
    __syncthreads();
    int count = scount;

    // lane -> 2 adjacent pixels on one row: p0 = 2*lane, p1 = 2*lane+1
    int p0 = lane * 2;
    int prow = p0 >> 3;          // 0..7
    int pcol = p0 & 7;           // 0,2,4,6

    int row  = blockIdx.y * TILE_H + prow;
    int col0 = blockIdx.x * TILE_W + pcol;
    float py  = (float)row + 0.5f;
    float px0 = (float)col0 + 0.5f;
    float px1 = px0 + 1.0f;

    float zmin0 = BIGF, zmin1 = BIGF;

    const unsigned* list = &g_tilelist[(long)slot * CAP];
    const float4*   tri  = &g_tri[(long)b * MAXF * 4];

    // warp w processes chunks w, w+4, w+8, ...  (CH == 32: one entry per lane)
    for (int base = warp * CH; base < count; base += NWARPS * CH) {
        int n = min(CH, count - base);

        // refresh warp-wide max of current partial z-mins (only decreases)
        float wzmax = fmaxf(zmin0, zmin1);
#pragma unroll
        for (int off = 16; off; off >>= 1)
            wzmax = fmaxf(wzmax, __shfl_xor_sync(0xffffffffu, wzmax, off));

        // z-cull + ballot compaction from ONE packed load
        bool keep = false;
        int fid = 0;
        if (lane < n) {
            unsigned e = list[base + lane];
            fid = (int)(e & FMASK);
            keep = (__uint_as_float(e & ZMASK) <= wzmax);
        }
        unsigned bal = __ballot_sync(0xffffffffu, keep);
        int nsurv = __popc(bal);
        if (keep) {
            int pos = __popc(bal & ((1u << lane) - 1u));
            sidx[warp][pos] = fid;
        }
        __syncwarp();
        if (nsurv == 0) continue;

        // stage only survivors' triangle data (4 float4 per entry)
        for (int i = lane; i < nsurv * 4; i += 32)
            sdata[warp][i] = tri[(long)sidx[warp][i >> 2] * 4 + (i & 3)];
        __syncwarp();

        for (int j = 0; j < nsurv; j++) {
            float4 d0 = sdata[warp][j * 4 + 0];
            float4 d1 = sdata[warp][j * 4 + 1];
            float4 d2 = sdata[warp][j * 4 + 2];
            float4 d3 = sdata[warp][j * 4 + 3];
            // row-shared terms (reference rounding preserved)
            float a0 = __fmul_rn(d0.x, __fsub_rn(py, d0.w));
            float a1 = __fmul_rn(d1.x, __fsub_rn(py, d1.w));
            float a2 = __fmul_rn(d2.x, __fsub_rn(py, d2.w));
            // pixel 0
            {
                float w0 = __fsub_rn(a0, __fmul_rn(d0.y, __fsub_rn(px0, d0.z)));
                float w1 = __fsub_rn(a1, __fmul_rn(d1.y, __fsub_rn(px0, d1.z)));
                float w2 = __fsub_rn(a2, __fmul_rn(d2.y, __fsub_rn(px0, d2.z)));
                float wmn = fminf(fminf(w0, w1), w2);
                float wmx = fmaxf(fmaxf(w0, w1), w2);
                bool inside = (wmn >= 0.f) || (wmx <= 0.f);
                float zi = __fmaf_rn(w0, d3.x, __fmaf_rn(w1, d3.y, __fmul_rn(w2, d3.z)));
                if (inside && zi > EPSF) zmin0 = fminf(zmin0, zi);
            }
            // pixel 1
            {
                float w0 = __fsub_rn(a0, __fmul_rn(d0.y, __fsub_rn(px1, d0.z)));
                float w1 = __fsub_rn(a1, __fmul_rn(d1.y, __fsub_rn(px1, d1.z)));
                float w2 = __fsub_rn(a2, __fmul_rn(d2.y, __fsub_rn(px1, d2.z)));
                float wmn = fminf(fminf(w0, w1), w2);
                float wmx = fmaxf(fmaxf(w0, w1), w2);
                bool inside = (wmn >= 0.f) || (wmx <= 0.f);
                float zi = __fmaf_rn(w0, d3.x, __fmaf_rn(w1, d3.y, __fmul_rn(w2, d3.z)));
                if (inside && zi > EPSF) zmin1 = fminf(zmin1, zi);
            }
        }
        __syncwarp();
    }

    // merge 4 warps' partial minima
    szmin[warp][p0]     = zmin0;
    szmin[warp][p0 + 1] = zmin1;
    __syncthreads();

    if (tid < 64) {
        int p = tid;
        float z = fminf(fminf(szmin[0][p], szmin[1][p]),
                        fminf(szmin[2][p], szmin[3][p]));
        int r = blockIdx.y * TILE_H + (p >> 3);
        int c = blockIdx.x * TILE_W + (p & 7);
        if (r < H && c < W) {
            long off = ((long)b * H + r) * W + c;
            out[off] = (z < 0.5f * BIGF) ? z : -1.f;
        }
    }
}

extern "C" void kernel_launch(void* const* d_in, const int* in_sizes, int n_in,
                              void* d_out, int out_size) {
    const float* mesh    = (const float*)d_in[0];
    const float* Rm      = (const float*)d_in[1];
    const float* tv      = (const float*)d_in[2];
    const float* focal   = (const float*)d_in[3];
    const float* princpt = (const float*)d_in[4];
    const int*   face    = (const int*)  d_in[5];
    float* out = (float*)d_out;

    int B = in_sizes[1] / 9;            // R is (B,3,3)
    int V = in_sizes[0] / (3 * B);      // mesh is (B,V,3)
    int F = in_sizes[5] / 3;            // face is (F,3)
    int HW = out_size / B;              // out is (B,1,H,W)
    int W = (int)(sqrt((double)HW) + 0.5);
    int H = HW / W;
    int ntx = (W + TILE_W - 1) / TILE_W;
    int nty = (H + TILE_H - 1) / TILE_H;

    int nwarp = B * F;                   // one warp per (b,f)
    dr_setup_bin_kernel<<<(nwarp + (NT / 32) - 1) / (NT / 32), NT>>>(
        mesh, Rm, tv, focal, princpt, face, B, V, F, ntx, nty);
    dim3 grid(ntx, nty, B);
    dr_raster_kernel<<<grid, NT_R>>>(out, W, H, ntx);
}

// round 17
// speedup vs baseline: 9.0000x; 1.1694x over previous
#include <cuda_runtime.h>
#include <math.h>

#define EPSF 1e-8f
#define BIGF 1e10f
#define MAXB 8
#define MAXF 4096

#define TILE_W 8
#define TILE_H 8
#define NT_R   128         // raster: 4 warps; each covers all 64 px, 1/4 of list
#define NWARPS 4
#define NT     128         // setup_bin block size (4 warps = 4 faces per block)

#define MAXBL    4         // batches supported by the bin lists
#define MAXTILES 1024      // 32x32 tiles for 256x256 at 8x8
#define CAP      2048      // per-tile list capacity (> F always)
#define CH       32        // per-warp chunk size (raster)

#define ZMASK  0xFFFFF800u   // top 21 bits: truncated positive-float zlo
#define FMASK  0x000007FFu   // bottom 11 bits: face id (F < 2048)
#define BIGF_BITS 0x501502F9u // __float_as_uint(1e10f)

// Scratch (device globals; zero-initialized at load; raster restores zeros
// so every graph replay sees identical state)
__device__ float4 g_tri[MAXB * MAXF * 4];       // e0,e1,e2,iz per triangle (by face id)
__device__ int    g_tilecnt[MAXBL * MAXTILES];
__device__ unsigned g_tilelist[MAXBL * MAXTILES * CAP];  // packed (zlo21 | fid11)
// per-tile occlusion cap, stored as (BIGF_BITS - zhi_bits) so that the
// zero-initialized state decodes to BIGF ("no information"); updated with
// atomicMax by full-coverage instances in bin; reset to 0 by raster.
__device__ unsigned g_tilecap[MAXBL * MAXTILES];

// Conservative interval of affine w over a pixel-center rectangle:
// wc at rect center, radius = |ex|*hy + |ey|*hx, padded for fp slop.
__device__ __forceinline__ void edge_range(float ex, float ey, float ax, float ay,
                                           float cx, float cy, float hx, float hy,
                                           float& wmin, float& wmax) {
    float wc = ex * (cy - ay) - ey * (cx - ax);
    float r  = fabsf(ex) * hy + fabsf(ey) * hx;
    float pad = 1e-5f * (fabsf(wc) + r) + 1e-5f;
    wmin = wc - r - pad;
    wmax = wc + r + pad;
}

// Fused setup + bin, ONE WARP PER (batch, face).
// All 32 lanes redundantly compute the projection/edge setup, lanes 0-3 store
// the 4 float4s of g_tri, then the 32 lanes walk the candidate tile range in
// parallel pushing packed (zlo | face id) entries into per-tile lists.
// Full-coverage instances additionally publish a conservative per-tile zmin
// upper bound (zhi) via atomicMax on the inverted-bits cap.
__global__ __launch_bounds__(NT)
void dr_setup_bin_kernel(const float* __restrict__ mesh,
                         const float* __restrict__ Rm,
                         const float* __restrict__ tv,
                         const float* __restrict__ focal,
                         const float* __restrict__ princpt,
                         const int*   __restrict__ face,
                         int B, int V, int F, int ntx, int nty) {
    int warp = threadIdx.x >> 5;
    int lane = threadIdx.x & 31;
    int idx = blockIdx.x * (NT / 32) + warp;      // global warp id = (b,f)
    if (idx >= B * F) return;
    int b = idx / F;
    int f = idx - b * F;

    const float* Rb = Rm + b * 9;
    float t0 = tv[b * 3 + 0], t1 = tv[b * 3 + 1], t2 = tv[b * 3 + 2];
    float fx = focal[b * 2 + 0], fy = focal[b * 2 + 1];
    float cx = princpt[b * 2 + 0], cy = princpt[b * 2 + 1];

    float X[3], Y[3], Z[3];
#pragma unroll
    for (int k = 0; k < 3; k++) {
        int v = face[f * 3 + k];
        const float* m = mesh + ((long)b * V + v) * 3;
        float m0 = m[0], m1 = m[1], m2 = m[2];
        // einsum sum order j=0..2, then + t  (exact rn ops, no contraction)
        float c0 = __fadd_rn(__fadd_rn(__fmul_rn(Rb[0], m0), __fmul_rn(Rb[1], m1)), __fmul_rn(Rb[2], m2));
        float c1 = __fadd_rn(__fadd_rn(__fmul_rn(Rb[3], m0), __fmul_rn(Rb[4], m1)), __fmul_rn(Rb[5], m2));
        float c2 = __fadd_rn(__fadd_rn(__fmul_rn(Rb[6], m0), __fmul_rn(Rb[7], m1)), __fmul_rn(Rb[8], m2));
        c0 = __fadd_rn(c0, t0);
        c1 = __fadd_rn(c1, t1);
        c2 = __fadd_rn(c2, t2);
        float zs = (fabsf(c2) > EPSF) ? c2 : EPSF;
        X[k] = __fadd_rn(__fdiv_rn(__fmul_rn(fx, c0), zs), cx);
        Y[k] = __fadd_rn(__fdiv_rn(__fmul_rn(fy, c1), zs), cy);
        Z[k] = c2;
    }

    // area = (x1-x0)*(y2-y0) - (y1-y0)*(x2-x0)   (reference rounding)
    float area = __fsub_rn(__fmul_rn(__fsub_rn(X[1], X[0]), __fsub_rn(Y[2], Y[0])),
                           __fmul_rn(__fsub_rn(Y[1], Y[0]), __fsub_rn(X[2], X[0])));
    if (!(fabsf(area) > EPSF)) return;                       // invalid -> whole warp exits
    if (!(fminf(Z[0], fminf(Z[1], Z[2])) > EPSF)) return;

    float iz0 = __fdiv_rn(Z[0], area);
    float iz1 = __fdiv_rn(Z[1], area);
    float iz2 = __fdiv_rn(Z[2], area);

    float4 e0 = make_float4(__fsub_rn(X[2], X[1]), __fsub_rn(Y[2], Y[1]), X[1], Y[1]);
    float4 e1 = make_float4(__fsub_rn(X[0], X[2]), __fsub_rn(Y[0], Y[2]), X[2], Y[2]);
    float4 e2 = make_float4(__fsub_rn(X[1], X[0]), __fsub_rn(Y[1], Y[0]), X[0], Y[0]);
    float4 e3 = make_float4(iz0, iz1, iz2, 0.f);

    // lanes 0-3 each store one float4 of the setup record
    float4* o = &g_tri[((long)b * MAXF + f) * 4];
    if (lane == 0) o[0] = e0;
    else if (lane == 1) o[1] = e1;
    else if (lane == 2) o[2] = e2;
    else if (lane == 3) o[3] = e3;

    float xmin = fminf(X[0], fminf(X[1], X[2]));
    float xmax = fmaxf(X[0], fmaxf(X[1], X[2]));
    float ymin = fminf(Y[0], fminf(Y[1], Y[2]));
    float ymax = fmaxf(Y[0], fmaxf(Y[1], Y[2]));

    // per-triangle z gradient (affine zi = w0*iz0 + w1*iz1 + w2*iz2):
    // dzi/dpx = -gx, dzi/dpy = +gy ; radius over an 8x8 tile is constant.
    float gx = e0.y * iz0 + e1.y * iz1 + e2.y * iz2;
    float gy = e0.x * iz0 + e1.x * iz1 + e2.x * iz2;
    float rz = fabsf(gx) * 3.5f + fabsf(gy) * 3.5f;

    // conservative candidate tile range (extra tiles rejected by tests below)
    int tx0 = max(0, (int)floorf((xmin - ((float)TILE_W - 0.5f)) * (1.f / TILE_W)));
    int tx1 = min(ntx - 1, (int)floorf((xmax - 0.5f) * (1.f / TILE_W)) + 1);
    int ty0 = max(0, (int)floorf((ymin - ((float)TILE_H - 0.5f)) * (1.f / TILE_H)));
    int ty1 = min(nty - 1, (int)floorf((ymax - 0.5f) * (1.f / TILE_H)) + 1);
    if (tx1 < tx0 || ty1 < ty0) return;
    int nx = tx1 - tx0 + 1;
    int ntiles = nx * (ty1 - ty0 + 1);

    for (int i = lane; i < ntiles; i += 32) {
        int tilex = tx0 + (i % nx);
        int tiley = ty0 + (i / nx);
        float tminx = (float)(tilex * TILE_W) + 0.5f;
        float tmaxx = (float)(tilex * TILE_W + TILE_W - 1) + 0.5f;
        float tminy = (float)(tiley * TILE_H) + 0.5f;
        float tmaxy = (float)(tiley * TILE_H + TILE_H - 1) + 0.5f;
        // bbox pre-filter (same as before)
        if (xmax >= tminx && xmin <= tmaxx && ymax >= tminy && ymin <= tmaxy) {
            float tcx = 0.5f * (tminx + tmaxx);
            float tcy = 0.5f * (tminy + tmaxy);
            float thx = 0.5f * (tmaxx - tminx);
            float thy = 0.5f * (tmaxy - tminy);
            float mn0, mx0, mn1, mx1, mn2, mx2;
            edge_range(e0.x, e0.y, e0.z, e0.w, tcx, tcy, thx, thy, mn0, mx0);
            edge_range(e1.x, e1.y, e1.z, e1.w, tcx, tcy, thx, thy, mn1, mx1);
            edge_range(e2.x, e2.y, e2.z, e2.w, tcx, tcy, thx, thy, mn2, mx2);
            bool pos_ok = (mx0 >= 0.f) && (mx1 >= 0.f) && (mx2 >= 0.f);
            bool neg_ok = (mn0 <= 0.f) && (mn1 <= 0.f) && (mn2 <= 0.f);
            if (pos_ok || neg_ok) {
                // conservative z interval of zi over ALL pixel centers of this
                // tile: center value +/- radius +/- pad (pad scales with term
                // magnitudes -> dominates every fp rounding difference).
                float wc0 = e0.x * (tcy - e0.w) - e0.y * (tcx - e0.z);
                float wc1 = e1.x * (tcy - e1.w) - e1.y * (tcx - e1.z);
                float wc2 = e2.x * (tcy - e2.w) - e2.y * (tcx - e2.z);
                float tz0 = wc0 * iz0, tz1 = wc1 * iz1, tz2 = wc2 * iz2;
                float zc = tz0 + tz1 + tz2;
                float pad = 1e-4f * (fabsf(tz0) + fabsf(tz1) + fabsf(tz2) + rz) + 1e-6f;
                float zlo = fmaxf(zc - rz - pad, 0.f);
                // truncate down to 21 bits (positive float: smaller bits ->
                // smaller value -> still a lower bound), pack face id in low 11
                unsigned entry = (__float_as_uint(zlo) & ZMASK) | (unsigned)f;

                int slot = b * MAXTILES + tiley * ntx + tilex;
                int p = atomicAdd(&g_tilecnt[slot], 1);   // p < F <= CAP always
                g_tilelist[(long)slot * CAP + p] = entry;

                // full coverage: even the padded worst case keeps uniform sign
                // -> every tile pixel contributes zi <= zhi -> final per-pixel
                // zmin <= zhi. Publish as inverted-bits atomicMax (zero = BIGF).
                bool full = ((mn0 >= 0.f) && (mn1 >= 0.f) && (mn2 >= 0.f)) ||
                            ((mx0 <= 0.f) && (mx1 <= 0.f) && (mx2 <= 0.f));
                if (full) {
                    float zhi = zc + rz + pad;
                    atomicMax(&g_tilecap[slot], BIGF_BITS - __float_as_uint(zhi));
                }
            }
        }
    }
}

// 8x8 pixel tile per block, 128 threads = 4 warps. Every warp covers all 64
// pixels (2 adjacent px/lane), processes a disjoint quarter of the tile's list.
// Z-occlusion cull BEFORE staging, from a SINGLE packed load, seeded by the
// per-tile occlusion cap so far triangles are culled from the FIRST chunk.
// Survivors ballot-compacted; only their data staged; inner loop branch-free.
__global__ __launch_bounds__(NT_R)
void dr_raster_kernel(float* __restrict__ out, int W, int H, int ntx) {
    __shared__ float4 sdata[NWARPS][CH * 4];
    __shared__ int    sidx[NWARPS][CH];
    __shared__ float  szmin[NWARPS][65];   // [warp][pixel], padded
    __shared__ int    scount;
    __shared__ float  scap;

    int b = blockIdx.z;
    int tile = blockIdx.y * ntx + blockIdx.x;
    int slot = b * MAXTILES + tile;

    int tid  = threadIdx.x;
    int warp = tid >> 5;
    int lane = tid & 31;

    if (tid == 0) {
        scount = g_tilecnt[slot];
        g_tilecnt[slot] = 0;                 // restore zeros for next replay
        unsigned capv = g_tilecap[slot];
        g_tilecap[slot] = 0;
        scap = __uint_as_float(BIGF_BITS - capv);   // capv==0 -> BIGF
    }
    __syncthreads();
    int count = scount;
    float zcap = scap;

    // lane -> 2 adjacent pixels on one row: p0 = 2*lane, p1 = 2*lane+1
    int p0 = lane * 2;
    int prow = p0 >> 3;          // 0..7
    int pcol = p0 & 7;           // 0,2,4,6

    int row  = blockIdx.y * TILE_H + prow;
    int col0 = blockIdx.x * TILE_W + pcol;
    float py  = (float)row + 0.5f;
    float px0 = (float)col0 + 0.5f;
    float px1 = px0 + 1.0f;

    float zmin0 = BIGF, zmin1 = BIGF;

    const unsigned* list = &g_tilelist[(long)slot * CAP];
    const float4*   tri  = &g_tri[(long)b * MAXF * 4];

    // warp w processes chunks w, w+4, w+8, ...  (CH == 32: one entry per lane)
    for (int base = warp * CH; base < count; base += NWARPS * CH) {
        int n = min(CH, count - base);

        // warp-wide max of current partial z-mins, clamped by the tile cap
        float wzmax = fmaxf(zmin0, zmin1);
#pragma unroll
        for (int off = 16; off; off >>= 1)
            wzmax = fmaxf(wzmax, __shfl_xor_sync(0xffffffffu, wzmax, off));
        wzmax = fminf(wzmax, zcap);

        // z-cull + ballot compaction from ONE packed load
        bool keep = false;
        int fid = 0;
        if (lane < n) {
            unsigned e = list[base + lane];
            fid = (int)(e & FMASK);
            keep = (__uint_as_float(e & ZMASK) <= wzmax);
        }
        unsigned bal = __ballot_sync(0xffffffffu, keep);
        int nsurv = __popc(bal);
        if (keep) {
            int pos = __popc(bal & ((1u << lane) - 1u));
            sidx[warp][pos] = fid;
        }
        __syncwarp();
        if (nsurv == 0) continue;

        // stage only survivors' triangle data (4 float4 per entry)
        for (int i = lane; i < nsurv * 4; i += 32)
            sdata[warp][i] = tri[(long)sidx[warp][i >> 2] * 4 + (i & 3)];
        __syncwarp();

        for (int j = 0; j < nsurv; j++) {
            float4 d0 = sdata[warp][j * 4 + 0];
            float4 d1 = sdata[warp][j * 4 + 1];
            float4 d2 = sdata[warp][j * 4 + 2];
            float4 d3 = sdata[warp][j * 4 + 3];
            // row-shared terms (reference rounding preserved)
            float a0 = __fmul_rn(d0.x, __fsub_rn(py, d0.w));
            float a1 = __fmul_rn(d1.x, __fsub_rn(py, d1.w));
            float a2 = __fmul_rn(d2.x, __fsub_rn(py, d2.w));
            // pixel 0
            {
                float w0 = __fsub_rn(a0, __fmul_rn(d0.y, __fsub_rn(px0, d0.z)));
                float w1 = __fsub_rn(a1, __fmul_rn(d1.y, __fsub_rn(px0, d1.z)));
                float w2 = __fsub_rn(a2, __fmul_rn(d2.y, __fsub_rn(px0, d2.z)));
                float wmn = fminf(fminf(w0, w1), w2);
                float wmx = fmaxf(fmaxf(w0, w1), w2);
                bool inside = (wmn >= 0.f) || (wmx <= 0.f);
                float zi = __fmaf_rn(w0, d3.x, __fmaf_rn(w1, d3.y, __fmul_rn(w2, d3.z)));
                if (inside && zi > EPSF) zmin0 = fminf(zmin0, zi);
            }
            // pixel 1
            {
                float w0 = __fsub_rn(a0, __fmul_rn(d0.y, __fsub_rn(px1, d0.z)));
                float w1 = __fsub_rn(a1, __fmul_rn(d1.y, __fsub_rn(px1, d1.z)));
                float w2 = __fsub_rn(a2, __fmul_rn(d2.y, __fsub_rn(px1, d2.z)));
                float wmn = fminf(fminf(w0, w1), w2);
                float wmx = fmaxf(fmaxf(w0, w1), w2);
                bool inside = (wmn >= 0.f) || (wmx <= 0.f);
                float zi = __fmaf_rn(w0, d3.x, __fmaf_rn(w1, d3.y, __fmul_rn(w2, d3.z)));
                if (inside && zi > EPSF) zmin1 = fminf(zmin1, zi);
            }
        }
        __syncwarp();
    }

    // merge 4 warps' partial minima
    szmin[warp][p0]     = zmin0;
    szmin[warp][p0 + 1] = zmin1;
    __syncthreads();

    if (tid < 64) {
        int p = tid;
        float z = fminf(fminf(szmin[0][p], szmin[1][p]),
                        fminf(szmin[2][p], szmin[3][p]));
        int r = blockIdx.y * TILE_H + (p >> 3);
        int c = blockIdx.x * TILE_W + (p & 7);
        if (r < H && c < W) {
            long off = ((long)b * H + r) * W + c;
            out[off] = (z < 0.5f * BIGF) ? z : -1.f;
        }
    }
}

extern "C" void kernel_launch(void* const* d_in, const int* in_sizes, int n_in,
                              void* d_out, int out_size) {
    const float* mesh    = (const float*)d_in[0];
    const float* Rm      = (const float*)d_in[1];
    const float* tv      = (const float*)d_in[2];
    const float* focal   = (const float*)d_in[3];
    const float* princpt = (const float*)d_in[4];
    const int*   face    = (const int*)  d_in[5];
    float* out = (float*)d_out;

    int B = in_sizes[1] / 9;            // R is (B,3,3)
    int V = in_sizes[0] / (3 * B);      // mesh is (B,V,3)
    int F = in_sizes[5] / 3;            // face is (F,3)
    int HW = out_size / B;              // out is (B,1,H,W)
    int W = (int)(sqrt((double)HW) + 0.5);
    int H = HW / W;
    int ntx = (W + TILE_W - 1) / TILE_W;
    int nty = (H + TILE_H - 1) / TILE_H;

    int nwarp = B * F;                   // one warp per (b,f)
    dr_setup_bin_kernel<<<(nwarp + (NT / 32) - 1) / (NT / 32), NT>>>(
        mesh, Rm, tv, focal, princpt, face, B, V, F, ntx, nty);
    dim3 grid(ntx, nty, B);
    dr_raster_kernel<<<grid, NT_R>>>(out, W, H, ntx);
}